// round 4
// baseline (speedup 1.0000x reference)
#include <cuda_runtime.h>
#include <math.h>

// Problem constants (B=2, T=2048, D=1024, H=16, hd=64)
#define BT 4096          // B*T rows
#define DMODEL 1024
#define D3 3072
#define NHEAD 16
#define HD 64
#define TQ 2048

// Scratch (device globals: runtime allocation is forbidden).
__device__ float g_qkv[(size_t)BT * D3];     // 48 MB
__device__ float g_att[(size_t)BT * DMODEL]; // 16 MB

// ---------------------------------------------------------------------------
// Diagnostic pre-fills: if a downstream stage silently fails, the constant
// propagates and produces a *distinct* rel_err signature instead of 0.874.
// ---------------------------------------------------------------------------
__global__ __launch_bounds__(256) void fill_qkv_kernel()
{
    size_t n = (size_t)BT * D3;
    for (size_t i = blockIdx.x * 256ull + threadIdx.x; i < n;
         i += (size_t)gridDim.x * 256ull)
        g_qkv[i] = 0.05f;
}
__global__ __launch_bounds__(256) void fill_att_kernel()
{
    size_t n = (size_t)BT * DMODEL;
    for (size_t i = blockIdx.x * 256ull + threadIdx.x; i < n;
         i += (size_t)gridDim.x * 256ull)
        g_att[i] = 0.03f;
}

// ---------------------------------------------------------------------------
// Tiled NT GEMM: C[M,N] = A[M,K] @ B[N,K]^T (+bias).  BM=BN=64, BK=16,
// 256 threads, 4x4 per thread. a_gatt: A = g_att. c_gqkv: C = g_qkv.
// ---------------------------------------------------------------------------
__global__ __launch_bounds__(256) void gemm_nt(
    const float* __restrict__ Ap, const float* __restrict__ B,
    const float* __restrict__ bias, float* __restrict__ Cp,
    int M, int N, int K, int a_gatt, int c_gqkv)
{
    const float* A = a_gatt ? (const float*)g_att : Ap;
    float* C = c_gqkv ? (float*)g_qkv : Cp;

    __shared__ float As[16][68];
    __shared__ float Bs[16][68];
    const int tid = threadIdx.x;
    const int tx = tid & 15, ty = tid >> 4;
    const int m0 = blockIdx.y * 64, n0 = blockIdx.x * 64;

    float acc[4][4];
#pragma unroll
    for (int r = 0; r < 4; r++)
#pragma unroll
        for (int c = 0; c < 4; c++) acc[r][c] = 0.f;

    for (int k0 = 0; k0 < K; k0 += 16) {
#pragma unroll
        for (int i = 0; i < 4; i++) {
            int idx = tid + i * 256;        // 0..1023
            int mm = idx >> 4, kk = idx & 15;
            As[kk][mm] = A[(size_t)(m0 + mm) * K + k0 + kk];
            Bs[kk][mm] = B[(size_t)(n0 + mm) * K + k0 + kk];
        }
        __syncthreads();
#pragma unroll
        for (int k = 0; k < 16; k++) {
            float4 a4 = *(const float4*)&As[k][4 * ty];
            float4 b4 = *(const float4*)&Bs[k][4 * tx];
            float av[4] = {a4.x, a4.y, a4.z, a4.w};
            float bv[4] = {b4.x, b4.y, b4.z, b4.w};
#pragma unroll
            for (int r = 0; r < 4; r++)
#pragma unroll
                for (int c = 0; c < 4; c++) acc[r][c] += av[r] * bv[c];
        }
        __syncthreads();
    }

#pragma unroll
    for (int r = 0; r < 4; r++) {
        int row = m0 + 4 * ty + r;
        int col = n0 + 4 * tx;
        float4 v;
        float* vp = (float*)&v;
#pragma unroll
        for (int c = 0; c < 4; c++)
            vp[c] = acc[r][c] + (bias ? bias[col + c] : 0.f);
        *(float4*)&C[(size_t)row * N + col] = v;
    }
}

// ---------------------------------------------------------------------------
// RoPE (in-place on q,k sections of g_qkv). One block per row.
//   out[i]    = x[i]   *cos(t*f_i) - x[2i+1]*sin(t*f_i)   (i<32)
//   out[32+i] = x[32+i]*cos(t*f_i) + x[2i]  *sin(t*f_i),  f_i = 10000^(-i/32)
// Tables via double-precision trig of the fp32-rounded angle: immune to
// --use_fast_math MUFU approximations at large arguments (t up to 2047 rad).
// ---------------------------------------------------------------------------
__global__ __launch_bounds__(256) void rope_kernel()
{
    __shared__ float s[2048];
    const int row = blockIdx.x;
    const int t = row & (TQ - 1);
    float* base = g_qkv + (size_t)row * D3;

    for (int j = threadIdx.x; j < 2048; j += 256) s[j] = base[j];
    __syncthreads();
    for (int j = threadIdx.x; j < 2048; j += 256) {
        int i = j & (HD - 1);
        int hb = j - i;                      // start of this head's 64 dims
        int f = (i < 32) ? i : i - 32;
        // inv_freq in double, rounded to fp32 (matches jnp fp32 table build)
        float invf = (float)exp((double)f * (-9.210340371976184 / 32.0));
        float ang = (float)t * invf;         // fp32 product, like jax
        float cs = (float)cos((double)ang);
        float sn = (float)sin((double)ang);
        float self = s[j];
        float val;
        if (i < 32) val = self * cs - s[hb + 2 * i + 1] * sn;
        else        val = self * cs + s[hb + 2 * (i - 32)] * sn;
        base[j] = val;
    }
}

// ---------------------------------------------------------------------------
// Flash attention, fp32, STATIC shared (44.5 KB < 48 KB, no opt-in needed).
// One block per (batch*head, 64-query tile). 256 threads:
//   ty = tid/16 -> 4 query rows each; tx = tid%16.
// KV tile = 32. Per iter: S(64x32), online softmax, O += P(64x32) V(32x64).
// ---------------------------------------------------------------------------
__global__ __launch_bounds__(256) void flash_kernel()
{
    __shared__ float Qt[64][68];   // [d][qrow]   17408 B
    __shared__ float Kt[64][36];   // [d][krow]    9216 B
    __shared__ float Vs[32][68];   // [krow][d]    8704 B
    __shared__ float Ps[64][36];   // [qrow][krow] 9216 B

    const int bh = blockIdx.x;                 // 0..31
    const int qt = blockIdx.y;                 // 0..31
    const int b = bh >> 4, h = bh & 15;
    const float* Qg = g_qkv + (size_t)(b * TQ + qt * 64) * D3 + h * HD;
    const float* Kg = g_qkv + (size_t)(b * TQ) * D3 + DMODEL + h * HD;
    const float* Vg = Kg + DMODEL;

    const int tid = threadIdx.x;
    const int tx = tid & 15, ty = tid >> 4;
    const int tx2 = 2 * tx, tx4 = 4 * tx, ty4 = 4 * ty;

    // Load Q tile transposed: Qt[d][r]
    for (int idx = tid; idx < 4096; idx += 256) {
        int r = idx >> 6, d = idx & 63;
        Qt[d][r] = Qg[(size_t)r * D3 + d];
    }

    float m[4], l[4], o[4][4];
#pragma unroll
    for (int r = 0; r < 4; r++) {
        m[r] = -1e30f; l[r] = 0.f;
#pragma unroll
        for (int c = 0; c < 4; c++) o[r][c] = 0.f;
    }

    for (int kt = 0; kt < 64; kt++) {
        __syncthreads();  // prev PV done reading Vs/Ps (and Q load, iter 0)
        for (int idx = tid; idx < 2048; idx += 256) {
            int r = idx >> 6, d = idx & 63;     // r = krow 0..31
            size_t grow = (size_t)(kt * 32 + r) * D3 + d;
            Kt[d][r] = Kg[grow];
            Vs[r][d] = Vg[grow];
        }
        __syncthreads();

        // S[4ty+r][2tx+c] = sum_d Q[4ty+r][d] * K[2tx+c][d], scaled by 1/8
        float sacc[4][2];
#pragma unroll
        for (int r = 0; r < 4; r++) { sacc[r][0] = 0.f; sacc[r][1] = 0.f; }
#pragma unroll 8
        for (int k = 0; k < 64; k++) {
            float a0 = Qt[k][ty4 + 0], a1 = Qt[k][ty4 + 1];
            float a2 = Qt[k][ty4 + 2], a3 = Qt[k][ty4 + 3];
            float b0 = Kt[k][tx2 + 0], b1 = Kt[k][tx2 + 1];
            sacc[0][0] += a0 * b0; sacc[0][1] += a0 * b1;
            sacc[1][0] += a1 * b0; sacc[1][1] += a1 * b1;
            sacc[2][0] += a2 * b0; sacc[2][1] += a2 * b1;
            sacc[3][0] += a3 * b0; sacc[3][1] += a3 * b1;
        }

        float p[4][2];
#pragma unroll
        for (int r = 0; r < 4; r++) {
            sacc[r][0] *= 0.125f; sacc[r][1] *= 0.125f;
            float rm = fmaxf(sacc[r][0], sacc[r][1]);
            rm = fmaxf(rm, __shfl_xor_sync(0xffffffffu, rm, 8));
            rm = fmaxf(rm, __shfl_xor_sync(0xffffffffu, rm, 4));
            rm = fmaxf(rm, __shfl_xor_sync(0xffffffffu, rm, 2));
            rm = fmaxf(rm, __shfl_xor_sync(0xffffffffu, rm, 1));
            float mnew = fmaxf(m[r], rm);
            float corr = __expf(m[r] - mnew);
            p[r][0] = __expf(sacc[r][0] - mnew);
            p[r][1] = __expf(sacc[r][1] - mnew);
            float rs = p[r][0] + p[r][1];
            rs += __shfl_xor_sync(0xffffffffu, rs, 8);
            rs += __shfl_xor_sync(0xffffffffu, rs, 4);
            rs += __shfl_xor_sync(0xffffffffu, rs, 2);
            rs += __shfl_xor_sync(0xffffffffu, rs, 1);
            l[r] = l[r] * corr + rs;
            m[r] = mnew;
#pragma unroll
            for (int c = 0; c < 4; c++) o[r][c] *= corr;
        }

        // Write P
#pragma unroll
        for (int r = 0; r < 4; r++) {
            Ps[ty4 + r][tx2 + 0] = p[r][0];
            Ps[ty4 + r][tx2 + 1] = p[r][1];
        }
        __syncthreads();

        // O += P V  (out dims 4tx..4tx+3)
#pragma unroll 8
        for (int k = 0; k < 32; k++) {
            float v0 = Vs[k][tx4 + 0], v1 = Vs[k][tx4 + 1];
            float v2 = Vs[k][tx4 + 2], v3 = Vs[k][tx4 + 3];
#pragma unroll
            for (int r = 0; r < 4; r++) {
                float pr = Ps[ty4 + r][k];
                o[r][0] += pr * v0; o[r][1] += pr * v1;
                o[r][2] += pr * v2; o[r][3] += pr * v3;
            }
        }
    }

    // Normalize and write to (B,T,D) layout
#pragma unroll
    for (int r = 0; r < 4; r++) {
        float inv = 1.f / l[r];
        int trow = b * TQ + qt * 64 + ty4 + r;
        float4 v = make_float4(o[r][0] * inv, o[r][1] * inv,
                               o[r][2] * inv, o[r][3] * inv);
        *(float4*)&g_att[(size_t)trow * DMODEL + h * HD + tx4] = v;
    }
}

// ---------------------------------------------------------------------------
extern "C" void kernel_launch(void* const* d_in, const int* in_sizes, int n_in,
                              void* d_out, int out_size)
{
    // Identify inputs by unique element counts (robust to ordering):
    //   x: 4194304, w_qkv: 3145728, w_out: 1048576, b_out: 1024
    const float *x = 0, *w_qkv = 0, *w_out = 0, *b_out = 0;
    for (int i = 0; i < n_in; i++) {
        switch (in_sizes[i]) {
            case 4194304: x     = (const float*)d_in[i]; break;
            case 3145728: w_qkv = (const float*)d_in[i]; break;
            case 1048576: w_out = (const float*)d_in[i]; break;
            case 1024:    b_out = (const float*)d_in[i]; break;
        }
    }
    // Positional fallback (reference arg order) if size matching failed.
    if (!x && n_in >= 4) {
        x     = (const float*)d_in[0];
        w_qkv = (const float*)d_in[1];
        w_out = (const float*)d_in[2];
        b_out = (const float*)d_in[3];
    }
    float* out = (float*)d_out;

    // 0) Diagnostic pre-fills of device-global scratch.
    fill_qkv_kernel<<<4096, 256>>>();
    fill_att_kernel<<<2048, 256>>>();
    // 1) g_qkv = x @ w_qkv^T   (4096 x 3072)
    gemm_nt<<<dim3(D3 / 64, BT / 64), 256>>>(x, w_qkv, nullptr, nullptr,
                                             BT, D3, DMODEL, 0, 1);
    // 2) RoPE in-place on q,k sections of g_qkv
    rope_kernel<<<BT, 256>>>();
    // 3) attention: g_att = softmax(QK^T/8) V
    flash_kernel<<<dim3(32, 32), 256>>>();
    // 4) out = g_att @ w_out^T + b_out
    gemm_nt<<<dim3(DMODEL / 64, BT / 64), 256>>>(nullptr, w_out, b_out, out,
                                                 BT, DMODEL, DMODEL, 1, 0);
}

// round 5
// speedup vs baseline: 1.2146x; 1.2146x over previous
#include <cuda_runtime.h>
#include <math.h>

// Problem constants (B=2, T=2048, D=1024, H=16, hd=64)
#define BT 4096          // B*T rows
#define DMODEL 1024
#define D3 3072
#define NHEAD 16
#define HD 64
#define TQ 2048

// Scratch (device globals: runtime allocation is forbidden).
__device__ float g_qkv[(size_t)BT * D3];     // 48 MB
__device__ float g_att[(size_t)BT * DMODEL]; // 16 MB
__device__ float g_cos_tab[TQ * 32];         // 256 KB
__device__ float g_sin_tab[TQ * 32];         // 256 KB

// ---------------------------------------------------------------------------
// Pre-fills of scratch (kept from the first passing round).
// ---------------------------------------------------------------------------
__global__ __launch_bounds__(256) void fill_qkv_kernel()
{
    size_t n = (size_t)BT * D3;
    for (size_t i = blockIdx.x * 256ull + threadIdx.x; i < n;
         i += (size_t)gridDim.x * 256ull)
        g_qkv[i] = 0.05f;
}
__global__ __launch_bounds__(256) void fill_att_kernel()
{
    size_t n = (size_t)BT * DMODEL;
    for (size_t i = blockIdx.x * 256ull + threadIdx.x; i < n;
         i += (size_t)gridDim.x * 256ull)
        g_att[i] = 0.03f;
}

// ---------------------------------------------------------------------------
// RoPE tables: 2048 positions x 32 freqs, DP trig of the fp32-rounded angle
// (bit-identical to the per-element math that passed in R4, hoisted out).
// ---------------------------------------------------------------------------
__global__ __launch_bounds__(256) void rope_table_kernel()
{
    int idx = blockIdx.x * 256 + threadIdx.x;   // 0..65535
    if (idx >= TQ * 32) return;
    int t = idx >> 5, f = idx & 31;
    float invf = (float)exp((double)f * (-9.210340371976184 / 32.0));
    float ang = (float)t * invf;                // fp32 product, like jax
    g_cos_tab[idx] = (float)cos((double)ang);
    g_sin_tab[idx] = (float)sin((double)ang);
}

// ---------------------------------------------------------------------------
// Tiled NT GEMM: C[M,N] = A[M,K] @ B[N,K]^T (+bias).  BM=BN=64, BK=16,
// 256 threads, 4x4 per thread. a_gatt: A = g_att. c_gqkv: C = g_qkv.
// ---------------------------------------------------------------------------
__global__ __launch_bounds__(256) void gemm_nt(
    const float* __restrict__ Ap, const float* __restrict__ B,
    const float* __restrict__ bias, float* __restrict__ Cp,
    int M, int N, int K, int a_gatt, int c_gqkv)
{
    const float* A = a_gatt ? (const float*)g_att : Ap;
    float* C = c_gqkv ? (float*)g_qkv : Cp;

    __shared__ float As[16][68];
    __shared__ float Bs[16][68];
    const int tid = threadIdx.x;
    const int tx = tid & 15, ty = tid >> 4;
    const int m0 = blockIdx.y * 64, n0 = blockIdx.x * 64;

    float acc[4][4];
#pragma unroll
    for (int r = 0; r < 4; r++)
#pragma unroll
        for (int c = 0; c < 4; c++) acc[r][c] = 0.f;

    for (int k0 = 0; k0 < K; k0 += 16) {
#pragma unroll
        for (int i = 0; i < 4; i++) {
            int idx = tid + i * 256;        // 0..1023
            int mm = idx >> 4, kk = idx & 15;
            As[kk][mm] = A[(size_t)(m0 + mm) * K + k0 + kk];
            Bs[kk][mm] = B[(size_t)(n0 + mm) * K + k0 + kk];
        }
        __syncthreads();
#pragma unroll
        for (int k = 0; k < 16; k++) {
            float4 a4 = *(const float4*)&As[k][4 * ty];
            float4 b4 = *(const float4*)&Bs[k][4 * tx];
            float av[4] = {a4.x, a4.y, a4.z, a4.w};
            float bv[4] = {b4.x, b4.y, b4.z, b4.w};
#pragma unroll
            for (int r = 0; r < 4; r++)
#pragma unroll
                for (int c = 0; c < 4; c++) acc[r][c] += av[r] * bv[c];
        }
        __syncthreads();
    }

#pragma unroll
    for (int r = 0; r < 4; r++) {
        int row = m0 + 4 * ty + r;
        int col = n0 + 4 * tx;
        float4 v;
        float* vp = (float*)&v;
#pragma unroll
        for (int c = 0; c < 4; c++)
            vp[c] = acc[r][c] + (bias ? bias[col + c] : 0.f);
        *(float4*)&C[(size_t)row * N + col] = v;
    }
}

// ---------------------------------------------------------------------------
// RoPE apply (in-place on q,k sections of g_qkv). One block per row.
//   out[i]    = x[i]   *cos(t*f_i) - x[2i+1]*sin(t*f_i)   (i<32)
//   out[32+i] = x[32+i]*cos(t*f_i) + x[2i]  *sin(t*f_i),  f = i&31
// Pure table lookups + memory traffic now (~64 MB total).
// ---------------------------------------------------------------------------
__global__ __launch_bounds__(256) void rope_kernel()
{
    __shared__ float s[2048];
    __shared__ float cs[32], sn[32];
    const int row = blockIdx.x;
    const int t = row & (TQ - 1);
    float* base = g_qkv + (size_t)row * D3;

    if (threadIdx.x < 32) {
        cs[threadIdx.x] = g_cos_tab[t * 32 + threadIdx.x];
        sn[threadIdx.x] = g_sin_tab[t * 32 + threadIdx.x];
    }
    for (int j = threadIdx.x; j < 2048; j += 256) s[j] = base[j];
    __syncthreads();
#pragma unroll
    for (int jj = 0; jj < 8; jj++) {
        int j = threadIdx.x + jj * 256;
        int i = j & (HD - 1);
        int hb = j - i;                      // start of this head's 64 dims
        int f = i & 31;
        float self = s[j];
        float val;
        if (i < 32) val = self * cs[f] - s[hb + 2 * i + 1] * sn[f];
        else        val = self * cs[f] + s[hb + 2 * (i - 32)] * sn[f];
        base[j] = val;
    }
}

// ---------------------------------------------------------------------------
// Flash attention, fp32, STATIC shared (44.5 KB < 48 KB, no opt-in needed).
// One block per (batch*head, 64-query tile). 256 threads:
//   ty = tid/16 -> 4 query rows each; tx = tid%16.
// KV tile = 32. Per iter: S(64x32), online softmax, O += P(64x32) V(32x64).
// ---------------------------------------------------------------------------
__global__ __launch_bounds__(256) void flash_kernel()
{
    __shared__ float Qt[64][68];   // [d][qrow]   17408 B
    __shared__ float Kt[64][36];   // [d][krow]    9216 B
    __shared__ float Vs[32][68];   // [krow][d]    8704 B
    __shared__ float Ps[64][36];   // [qrow][krow] 9216 B

    const int bh = blockIdx.x;                 // 0..31
    const int qt = blockIdx.y;                 // 0..31
    const int b = bh >> 4, h = bh & 15;
    const float* Qg = g_qkv + (size_t)(b * TQ + qt * 64) * D3 + h * HD;
    const float* Kg = g_qkv + (size_t)(b * TQ) * D3 + DMODEL + h * HD;
    const float* Vg = Kg + DMODEL;

    const int tid = threadIdx.x;
    const int tx = tid & 15, ty = tid >> 4;
    const int tx2 = 2 * tx, tx4 = 4 * tx, ty4 = 4 * ty;

    // Load Q tile transposed: Qt[d][r]
    for (int idx = tid; idx < 4096; idx += 256) {
        int r = idx >> 6, d = idx & 63;
        Qt[d][r] = Qg[(size_t)r * D3 + d];
    }

    float m[4], l[4], o[4][4];
#pragma unroll
    for (int r = 0; r < 4; r++) {
        m[r] = -1e30f; l[r] = 0.f;
#pragma unroll
        for (int c = 0; c < 4; c++) o[r][c] = 0.f;
    }

    for (int kt = 0; kt < 64; kt++) {
        __syncthreads();  // prev PV done reading Vs/Ps (and Q load, iter 0)
        for (int idx = tid; idx < 2048; idx += 256) {
            int r = idx >> 6, d = idx & 63;     // r = krow 0..31
            size_t grow = (size_t)(kt * 32 + r) * D3 + d;
            Kt[d][r] = Kg[grow];
            Vs[r][d] = Vg[grow];
        }
        __syncthreads();

        // S[4ty+r][2tx+c] = sum_d Q[4ty+r][d] * K[2tx+c][d], scaled by 1/8
        float sacc[4][2];
#pragma unroll
        for (int r = 0; r < 4; r++) { sacc[r][0] = 0.f; sacc[r][1] = 0.f; }
#pragma unroll 8
        for (int k = 0; k < 64; k++) {
            float a0 = Qt[k][ty4 + 0], a1 = Qt[k][ty4 + 1];
            float a2 = Qt[k][ty4 + 2], a3 = Qt[k][ty4 + 3];
            float b0 = Kt[k][tx2 + 0], b1 = Kt[k][tx2 + 1];
            sacc[0][0] += a0 * b0; sacc[0][1] += a0 * b1;
            sacc[1][0] += a1 * b0; sacc[1][1] += a1 * b1;
            sacc[2][0] += a2 * b0; sacc[2][1] += a2 * b1;
            sacc[3][0] += a3 * b0; sacc[3][1] += a3 * b1;
        }

        float p[4][2];
#pragma unroll
        for (int r = 0; r < 4; r++) {
            sacc[r][0] *= 0.125f; sacc[r][1] *= 0.125f;
            float rm = fmaxf(sacc[r][0], sacc[r][1]);
            rm = fmaxf(rm, __shfl_xor_sync(0xffffffffu, rm, 8));
            rm = fmaxf(rm, __shfl_xor_sync(0xffffffffu, rm, 4));
            rm = fmaxf(rm, __shfl_xor_sync(0xffffffffu, rm, 2));
            rm = fmaxf(rm, __shfl_xor_sync(0xffffffffu, rm, 1));
            float mnew = fmaxf(m[r], rm);
            float corr = __expf(m[r] - mnew);
            p[r][0] = __expf(sacc[r][0] - mnew);
            p[r][1] = __expf(sacc[r][1] - mnew);
            float rs = p[r][0] + p[r][1];
            rs += __shfl_xor_sync(0xffffffffu, rs, 8);
            rs += __shfl_xor_sync(0xffffffffu, rs, 4);
            rs += __shfl_xor_sync(0xffffffffu, rs, 2);
            rs += __shfl_xor_sync(0xffffffffu, rs, 1);
            l[r] = l[r] * corr + rs;
            m[r] = mnew;
#pragma unroll
            for (int c = 0; c < 4; c++) o[r][c] *= corr;
        }

        // Write P
#pragma unroll
        for (int r = 0; r < 4; r++) {
            Ps[ty4 + r][tx2 + 0] = p[r][0];
            Ps[ty4 + r][tx2 + 1] = p[r][1];
        }
        __syncthreads();

        // O += P V  (out dims 4tx..4tx+3)
#pragma unroll 8
        for (int k = 0; k < 32; k++) {
            float v0 = Vs[k][tx4 + 0], v1 = Vs[k][tx4 + 1];
            float v2 = Vs[k][tx4 + 2], v3 = Vs[k][tx4 + 3];
#pragma unroll
            for (int r = 0; r < 4; r++) {
                float pr = Ps[ty4 + r][k];
                o[r][0] += pr * v0; o[r][1] += pr * v1;
                o[r][2] += pr * v2; o[r][3] += pr * v3;
            }
        }
    }

    // Normalize and write to (B,T,D) layout
#pragma unroll
    for (int r = 0; r < 4; r++) {
        float inv = 1.f / l[r];
        int trow = b * TQ + qt * 64 + ty4 + r;
        float4 v = make_float4(o[r][0] * inv, o[r][1] * inv,
                               o[r][2] * inv, o[r][3] * inv);
        *(float4*)&g_att[(size_t)trow * DMODEL + h * HD + tx4] = v;
    }
}

// ---------------------------------------------------------------------------
extern "C" void kernel_launch(void* const* d_in, const int* in_sizes, int n_in,
                              void* d_out, int out_size)
{
    // Identify inputs by unique element counts (robust to ordering):
    //   x: 4194304, w_qkv: 3145728, w_out: 1048576, b_out: 1024
    const float *x = 0, *w_qkv = 0, *w_out = 0, *b_out = 0;
    for (int i = 0; i < n_in; i++) {
        switch (in_sizes[i]) {
            case 4194304: x     = (const float*)d_in[i]; break;
            case 3145728: w_qkv = (const float*)d_in[i]; break;
            case 1048576: w_out = (const float*)d_in[i]; break;
            case 1024:    b_out = (const float*)d_in[i]; break;
        }
    }
    // Positional fallback (reference arg order) if size matching failed.
    if (!x && n_in >= 4) {
        x     = (const float*)d_in[0];
        w_qkv = (const float*)d_in[1];
        w_out = (const float*)d_in[2];
        b_out = (const float*)d_in[3];
    }
    float* out = (float*)d_out;

    // 0) Pre-fills + RoPE tables (tables independent of inputs, cheap).
    fill_qkv_kernel<<<4096, 256>>>();
    fill_att_kernel<<<2048, 256>>>();
    rope_table_kernel<<<(TQ * 32 + 255) / 256, 256>>>();
    // 1) g_qkv = x @ w_qkv^T   (4096 x 3072)
    gemm_nt<<<dim3(D3 / 64, BT / 64), 256>>>(x, w_qkv, nullptr, nullptr,
                                             BT, D3, DMODEL, 0, 1);
    // 2) RoPE in-place on q,k sections of g_qkv (table-driven)
    rope_kernel<<<BT, 256>>>();
    // 3) attention: g_att = softmax(QK^T/8) V
    flash_kernel<<<dim3(32, 32), 256>>>();
    // 4) out = g_att @ w_out^T + b_out
    gemm_nt<<<dim3(DMODEL / 64, BT / 64), 256>>>(nullptr, w_out, b_out, out,
                                                 BT, DMODEL, DMODEL, 1, 0);
}

// round 6
// speedup vs baseline: 1.3972x; 1.1503x over previous
#include <cuda_runtime.h>
#include <math.h>

// Problem constants (B=2, T=2048, D=1024, H=16, hd=64)
#define BT 4096          // B*T rows
#define DMODEL 1024
#define D3 3072
#define NHEAD 16
#define HD 64
#define TQ 2048

// Scratch (device globals: runtime allocation is forbidden).
__device__ float g_qkv[(size_t)BT * D3];     // 48 MB
__device__ float g_att[(size_t)BT * DMODEL]; // 16 MB
__device__ float g_cos_tab[TQ * 32];         // 256 KB
__device__ float g_sin_tab[TQ * 32];         // 256 KB

// ---------------------------------------------------------------------------
// Pre-fills of scratch (kept from the first passing round).
// ---------------------------------------------------------------------------
__global__ __launch_bounds__(256) void fill_qkv_kernel()
{
    size_t n = (size_t)BT * D3;
    for (size_t i = blockIdx.x * 256ull + threadIdx.x; i < n;
         i += (size_t)gridDim.x * 256ull)
        g_qkv[i] = 0.05f;
}
__global__ __launch_bounds__(256) void fill_att_kernel()
{
    size_t n = (size_t)BT * DMODEL;
    for (size_t i = blockIdx.x * 256ull + threadIdx.x; i < n;
         i += (size_t)gridDim.x * 256ull)
        g_att[i] = 0.03f;
}

// ---------------------------------------------------------------------------
// RoPE tables: 2048 positions x 32 freqs (DP trig of fp32-rounded angle).
// ---------------------------------------------------------------------------
__global__ __launch_bounds__(256) void rope_table_kernel()
{
    int idx = blockIdx.x * 256 + threadIdx.x;   // 0..65535
    if (idx >= TQ * 32) return;
    int t = idx >> 5, f = idx & 31;
    float invf = (float)exp((double)f * (-9.210340371976184 / 32.0));
    float ang = (float)t * invf;                // fp32 product, like jax
    g_cos_tab[idx] = (float)cos((double)ang);
    g_sin_tab[idx] = (float)sin((double)ang);
}

// ---------------------------------------------------------------------------
// SGEMM NT: C[M,N] = A[M,K] @ B[N,K]^T (+bias). BM=BN=128, BK=16,
// 256 threads, 8x8 microtile. Smem K-major with pad 132 -> compute reads are
// contiguous float4; FFMA:crossbar = 1:1 (vs 1:2 in the old 64x64 kernel).
// a_gatt: A = g_att. c_gqkv: C = g_qkv.
// ---------------------------------------------------------------------------
__global__ __launch_bounds__(256, 2) void gemm_nt(
    const float* __restrict__ Ap, const float* __restrict__ B,
    const float* __restrict__ bias, float* __restrict__ Cp,
    int M, int N, int K, int a_gatt, int c_gqkv)
{
    const float* A = a_gatt ? (const float*)g_att : Ap;
    float* C = c_gqkv ? (float*)g_qkv : Cp;

    __shared__ float As[16][132];
    __shared__ float Bs[16][132];

    const int tid = threadIdx.x;
    const int tx = tid & 15, ty = tid >> 4;
    const int m0 = blockIdx.y * 128, n0 = blockIdx.x * 128;

    // Global-load mapping: thread covers row = tid>>1 (two tiles of 128 rows
    // handled as row, row: A rows and B rows), kbase = (tid&1)*8.
    const int lrow = tid >> 1;          // 0..127
    const int lk = (tid & 1) * 8;       // 0 or 8

    float acc[8][8];
#pragma unroll
    for (int r = 0; r < 8; r++)
#pragma unroll
        for (int c = 0; c < 8; c++) acc[r][c] = 0.f;

    for (int k0 = 0; k0 < K; k0 += 16) {
        // Load A[128][16] and B[128][16] slabs, store K-major.
        float4 av0 = *(const float4*)&A[(size_t)(m0 + lrow) * K + k0 + lk];
        float4 av1 = *(const float4*)&A[(size_t)(m0 + lrow) * K + k0 + lk + 4];
        float4 bv0 = *(const float4*)&B[(size_t)(n0 + lrow) * K + k0 + lk];
        float4 bv1 = *(const float4*)&B[(size_t)(n0 + lrow) * K + k0 + lk + 4];
        __syncthreads();   // previous compute done before overwriting smem
        As[lk + 0][lrow] = av0.x; As[lk + 1][lrow] = av0.y;
        As[lk + 2][lrow] = av0.z; As[lk + 3][lrow] = av0.w;
        As[lk + 4][lrow] = av1.x; As[lk + 5][lrow] = av1.y;
        As[lk + 6][lrow] = av1.z; As[lk + 7][lrow] = av1.w;
        Bs[lk + 0][lrow] = bv0.x; Bs[lk + 1][lrow] = bv0.y;
        Bs[lk + 2][lrow] = bv0.z; Bs[lk + 3][lrow] = bv0.w;
        Bs[lk + 4][lrow] = bv1.x; Bs[lk + 5][lrow] = bv1.y;
        Bs[lk + 6][lrow] = bv1.z; Bs[lk + 7][lrow] = bv1.w;
        __syncthreads();

#pragma unroll
        for (int k = 0; k < 16; k++) {
            float4 a0 = *(const float4*)&As[k][8 * ty];
            float4 a1 = *(const float4*)&As[k][8 * ty + 4];
            float4 b0 = *(const float4*)&Bs[k][8 * tx];
            float4 b1 = *(const float4*)&Bs[k][8 * tx + 4];
            float av[8] = {a0.x, a0.y, a0.z, a0.w, a1.x, a1.y, a1.z, a1.w};
            float bv[8] = {b0.x, b0.y, b0.z, b0.w, b1.x, b1.y, b1.z, b1.w};
#pragma unroll
            for (int r = 0; r < 8; r++)
#pragma unroll
                for (int c = 0; c < 8; c++) acc[r][c] += av[r] * bv[c];
        }
    }

#pragma unroll
    for (int r = 0; r < 8; r++) {
        int row = m0 + 8 * ty + r;
#pragma unroll
        for (int cc = 0; cc < 2; cc++) {
            int col = n0 + 8 * tx + 4 * cc;
            float4 v;
            v.x = acc[r][4 * cc + 0] + (bias ? bias[col + 0] : 0.f);
            v.y = acc[r][4 * cc + 1] + (bias ? bias[col + 1] : 0.f);
            v.z = acc[r][4 * cc + 2] + (bias ? bias[col + 2] : 0.f);
            v.w = acc[r][4 * cc + 3] + (bias ? bias[col + 3] : 0.f);
            *(float4*)&C[(size_t)row * N + col] = v;
        }
    }
}

// ---------------------------------------------------------------------------
// RoPE apply (in-place on q,k sections of g_qkv). One block per row.
// ---------------------------------------------------------------------------
__global__ __launch_bounds__(256) void rope_kernel()
{
    __shared__ float s[2048];
    __shared__ float cs[32], sn[32];
    const int row = blockIdx.x;
    const int t = row & (TQ - 1);
    float* base = g_qkv + (size_t)row * D3;

    if (threadIdx.x < 32) {
        cs[threadIdx.x] = g_cos_tab[t * 32 + threadIdx.x];
        sn[threadIdx.x] = g_sin_tab[t * 32 + threadIdx.x];
    }
    for (int j = threadIdx.x; j < 2048; j += 256) s[j] = base[j];
    __syncthreads();
#pragma unroll
    for (int jj = 0; jj < 8; jj++) {
        int j = threadIdx.x + jj * 256;
        int i = j & (HD - 1);
        int hb = j - i;
        int f = i & 31;
        float self = s[j];
        float val;
        if (i < 32) val = self * cs[f] - s[hb + 2 * i + 1] * sn[f];
        else        val = self * cs[f] + s[hb + 2 * (i - 32)] * sn[f];
        base[j] = val;
    }
}

// ---------------------------------------------------------------------------
// Flash attention, fp32, STATIC shared (44.5 KB). Unchanged from R5.
// ---------------------------------------------------------------------------
__global__ __launch_bounds__(256) void flash_kernel()
{
    __shared__ float Qt[64][68];   // [d][qrow]
    __shared__ float Kt[64][36];   // [d][krow]
    __shared__ float Vs[32][68];   // [krow][d]
    __shared__ float Ps[64][36];   // [qrow][krow]

    const int bh = blockIdx.x;
    const int qt = blockIdx.y;
    const int b = bh >> 4, h = bh & 15;
    const float* Qg = g_qkv + (size_t)(b * TQ + qt * 64) * D3 + h * HD;
    const float* Kg = g_qkv + (size_t)(b * TQ) * D3 + DMODEL + h * HD;
    const float* Vg = Kg + DMODEL;

    const int tid = threadIdx.x;
    const int tx = tid & 15, ty = tid >> 4;
    const int tx2 = 2 * tx, tx4 = 4 * tx, ty4 = 4 * ty;

    for (int idx = tid; idx < 4096; idx += 256) {
        int r = idx >> 6, d = idx & 63;
        Qt[d][r] = Qg[(size_t)r * D3 + d];
    }

    float m[4], l[4], o[4][4];
#pragma unroll
    for (int r = 0; r < 4; r++) {
        m[r] = -1e30f; l[r] = 0.f;
#pragma unroll
        for (int c = 0; c < 4; c++) o[r][c] = 0.f;
    }

    for (int kt = 0; kt < 64; kt++) {
        __syncthreads();
        for (int idx = tid; idx < 2048; idx += 256) {
            int r = idx >> 6, d = idx & 63;
            size_t grow = (size_t)(kt * 32 + r) * D3 + d;
            Kt[d][r] = Kg[grow];
            Vs[r][d] = Vg[grow];
        }
        __syncthreads();

        float sacc[4][2];
#pragma unroll
        for (int r = 0; r < 4; r++) { sacc[r][0] = 0.f; sacc[r][1] = 0.f; }
#pragma unroll 8
        for (int k = 0; k < 64; k++) {
            float a0 = Qt[k][ty4 + 0], a1 = Qt[k][ty4 + 1];
            float a2 = Qt[k][ty4 + 2], a3 = Qt[k][ty4 + 3];
            float b0 = Kt[k][tx2 + 0], b1 = Kt[k][tx2 + 1];
            sacc[0][0] += a0 * b0; sacc[0][1] += a0 * b1;
            sacc[1][0] += a1 * b0; sacc[1][1] += a1 * b1;
            sacc[2][0] += a2 * b0; sacc[2][1] += a2 * b1;
            sacc[3][0] += a3 * b0; sacc[3][1] += a3 * b1;
        }

        float p[4][2];
#pragma unroll
        for (int r = 0; r < 4; r++) {
            sacc[r][0] *= 0.125f; sacc[r][1] *= 0.125f;
            float rm = fmaxf(sacc[r][0], sacc[r][1]);
            rm = fmaxf(rm, __shfl_xor_sync(0xffffffffu, rm, 8));
            rm = fmaxf(rm, __shfl_xor_sync(0xffffffffu, rm, 4));
            rm = fmaxf(rm, __shfl_xor_sync(0xffffffffu, rm, 2));
            rm = fmaxf(rm, __shfl_xor_sync(0xffffffffu, rm, 1));
            float mnew = fmaxf(m[r], rm);
            float corr = __expf(m[r] - mnew);
            p[r][0] = __expf(sacc[r][0] - mnew);
            p[r][1] = __expf(sacc[r][1] - mnew);
            float rs = p[r][0] + p[r][1];
            rs += __shfl_xor_sync(0xffffffffu, rs, 8);
            rs += __shfl_xor_sync(0xffffffffu, rs, 4);
            rs += __shfl_xor_sync(0xffffffffu, rs, 2);
            rs += __shfl_xor_sync(0xffffffffu, rs, 1);
            l[r] = l[r] * corr + rs;
            m[r] = mnew;
#pragma unroll
            for (int c = 0; c < 4; c++) o[r][c] *= corr;
        }

#pragma unroll
        for (int r = 0; r < 4; r++) {
            Ps[ty4 + r][tx2 + 0] = p[r][0];
            Ps[ty4 + r][tx2 + 1] = p[r][1];
        }
        __syncthreads();

#pragma unroll 8
        for (int k = 0; k < 32; k++) {
            float v0 = Vs[k][tx4 + 0], v1 = Vs[k][tx4 + 1];
            float v2 = Vs[k][tx4 + 2], v3 = Vs[k][tx4 + 3];
#pragma unroll
            for (int r = 0; r < 4; r++) {
                float pr = Ps[ty4 + r][k];
                o[r][0] += pr * v0; o[r][1] += pr * v1;
                o[r][2] += pr * v2; o[r][3] += pr * v3;
            }
        }
    }

#pragma unroll
    for (int r = 0; r < 4; r++) {
        float inv = 1.f / l[r];
        int trow = b * TQ + qt * 64 + ty4 + r;
        float4 v = make_float4(o[r][0] * inv, o[r][1] * inv,
                               o[r][2] * inv, o[r][3] * inv);
        *(float4*)&g_att[(size_t)trow * DMODEL + h * HD + tx4] = v;
    }
}

// ---------------------------------------------------------------------------
extern "C" void kernel_launch(void* const* d_in, const int* in_sizes, int n_in,
                              void* d_out, int out_size)
{
    // Identify inputs by unique element counts (robust to ordering).
    const float *x = 0, *w_qkv = 0, *w_out = 0, *b_out = 0;
    for (int i = 0; i < n_in; i++) {
        switch (in_sizes[i]) {
            case 4194304: x     = (const float*)d_in[i]; break;
            case 3145728: w_qkv = (const float*)d_in[i]; break;
            case 1048576: w_out = (const float*)d_in[i]; break;
            case 1024:    b_out = (const float*)d_in[i]; break;
        }
    }
    if (!x && n_in >= 4) {
        x     = (const float*)d_in[0];
        w_qkv = (const float*)d_in[1];
        w_out = (const float*)d_in[2];
        b_out = (const float*)d_in[3];
    }
    float* out = (float*)d_out;

    // 0) Pre-fills + RoPE tables.
    fill_qkv_kernel<<<4096, 256>>>();
    fill_att_kernel<<<2048, 256>>>();
    rope_table_kernel<<<(TQ * 32 + 255) / 256, 256>>>();
    // 1) g_qkv = x @ w_qkv^T   (4096 x 3072), 128x128 tiles
    gemm_nt<<<dim3(D3 / 128, BT / 128), 256>>>(x, w_qkv, nullptr, nullptr,
                                               BT, D3, DMODEL, 0, 1);
    // 2) RoPE in-place
    rope_kernel<<<BT, 256>>>();
    // 3) attention
    flash_kernel<<<dim3(32, 32), 256>>>();
    // 4) out = g_att @ w_out^T + b_out
    gemm_nt<<<dim3(DMODEL / 128, BT / 128), 256>>>(nullptr, w_out, b_out, out,
                                                   BT, DMODEL, DMODEL, 1, 0);
}

// round 7
// speedup vs baseline: 1.7787x; 1.2731x over previous
#include <cuda_runtime.h>
#include <cuda_bf16.h>
#include <math.h>
#include <stdint.h>

// Problem constants (B=2, T=2048, D=1024, H=16, hd=64)
#define BT 4096          // B*T rows
#define DMODEL 1024
#define D3 3072
#define NHEAD 16
#define HD 64
#define TQ 2048

// Scratch (device globals: runtime allocation is forbidden).
__device__ float g_qkv[(size_t)BT * D3];     // 48 MB
__device__ float g_att[(size_t)BT * DMODEL]; // 16 MB
__device__ float g_cos_tab[TQ * 32];         // 256 KB
__device__ float g_sin_tab[TQ * 32];         // 256 KB

// ---------------------------------------------------------------------------
// Pre-fills of scratch (kept from the first passing round).
// ---------------------------------------------------------------------------
__global__ __launch_bounds__(256) void fill_qkv_kernel()
{
    size_t n = (size_t)BT * D3;
    for (size_t i = blockIdx.x * 256ull + threadIdx.x; i < n;
         i += (size_t)gridDim.x * 256ull)
        g_qkv[i] = 0.05f;
}
__global__ __launch_bounds__(256) void fill_att_kernel()
{
    size_t n = (size_t)BT * DMODEL;
    for (size_t i = blockIdx.x * 256ull + threadIdx.x; i < n;
         i += (size_t)gridDim.x * 256ull)
        g_att[i] = 0.03f;
}

// ---------------------------------------------------------------------------
// RoPE tables: 2048 positions x 32 freqs (DP trig of fp32-rounded angle).
// ---------------------------------------------------------------------------
__global__ __launch_bounds__(256) void rope_table_kernel()
{
    int idx = blockIdx.x * 256 + threadIdx.x;   // 0..65535
    if (idx >= TQ * 32) return;
    int t = idx >> 5, f = idx & 31;
    float invf = (float)exp((double)f * (-9.210340371976184 / 32.0));
    float ang = (float)t * invf;                // fp32 product, like jax
    g_cos_tab[idx] = (float)cos((double)ang);
    g_sin_tab[idx] = (float)sin((double)ang);
}

// ---------------------------------------------------------------------------
// MMA helpers (bf16 m16n8k16, ldmatrix from smem)
// ---------------------------------------------------------------------------
__device__ __forceinline__ uint32_t sptr(const void* p)
{
    return (uint32_t)__cvta_generic_to_shared(p);
}
__device__ __forceinline__ void ldsm4(uint32_t* r, uint32_t addr)
{
    asm volatile("ldmatrix.sync.aligned.m8n8.x4.shared.b16 {%0,%1,%2,%3}, [%4];"
                 : "=r"(r[0]), "=r"(r[1]), "=r"(r[2]), "=r"(r[3]) : "r"(addr));
}
__device__ __forceinline__ void ldsm2(uint32_t* r, uint32_t addr)
{
    asm volatile("ldmatrix.sync.aligned.m8n8.x2.shared.b16 {%0,%1}, [%2];"
                 : "=r"(r[0]), "=r"(r[1]) : "r"(addr));
}
__device__ __forceinline__ void mma16816(float* c, const uint32_t* a,
                                         const uint32_t* b)
{
    asm volatile(
        "mma.sync.aligned.m16n8k16.row.col.f32.bf16.bf16.f32 "
        "{%0,%1,%2,%3}, {%4,%5,%6,%7}, {%8,%9}, {%0,%1,%2,%3};"
        : "+f"(c[0]), "+f"(c[1]), "+f"(c[2]), "+f"(c[3])
        : "r"(a[0]), "r"(a[1]), "r"(a[2]), "r"(a[3]), "r"(b[0]), "r"(b[1]));
}

// ---------------------------------------------------------------------------
// bf16-split tensor GEMM NT: C[M,N] = A[M,K] @ B[N,K]^T (+bias).
// Split each fp32 x = hi + lo (both bf16). K is tripled in smem:
//   A segs [hi | lo | hi], B segs [hi | hi | lo]  ->  hi*hi + lo*hi + hi*lo.
// CTA: 128x128, BK=16 fp32 (48 bf16), 8 warps (2x4), warp tile 64x32.
// Error ~2^-16 per stage. Smem 28.7 KB static (2 CTAs/SM).
// ---------------------------------------------------------------------------
#define KSTRIDE 56   // bf16 elems per smem row (48 + 8 pad); 112 B

__global__ __launch_bounds__(256, 2) void gemm_nt_bf16x3(
    const float* __restrict__ Ap, const float* __restrict__ Bp,
    const float* __restrict__ bias, float* __restrict__ Cp,
    int M, int N, int K, int a_gatt, int c_gqkv)
{
    const float* A = a_gatt ? (const float*)g_att : Ap;
    float* C = c_gqkv ? (float*)g_qkv : Cp;

    __shared__ __align__(16) __nv_bfloat16 As[128 * KSTRIDE];
    __shared__ __align__(16) __nv_bfloat16 Bs[128 * KSTRIDE];

    const int tid = threadIdx.x;
    const int lane = tid & 31, warp = tid >> 5;
    const int wm = warp >> 2, wn = warp & 3;   // 2 x 4 warp grid
    const int m0 = blockIdx.y * 128, n0 = blockIdx.x * 128;

    const int lrow = tid >> 1;          // 0..127
    const int lk = (tid & 1) * 8;       // 0 or 8

    float acc[4][4][4];
#pragma unroll
    for (int mt = 0; mt < 4; mt++)
#pragma unroll
        for (int nt = 0; nt < 4; nt++)
#pragma unroll
            for (int i = 0; i < 4; i++) acc[mt][nt][i] = 0.f;

    // ldmatrix smem byte addresses (element row/k -> bytes)
    const int a_row = wm * 64 + (lane & 15);
    const int a_kof = (lane >> 4) * 8;
    uint32_t a_base = sptr(As) + (uint32_t)(a_row * KSTRIDE + a_kof) * 2u;
    const int b_row = wn * 32 + (lane & 7);
    const int b_kof = ((lane & 15) >> 3) * 8;
    uint32_t b_base = sptr(Bs) + (uint32_t)(b_row * KSTRIDE + b_kof) * 2u;

    __nv_bfloat16* Arow = &As[lrow * KSTRIDE];
    __nv_bfloat16* Brow = &Bs[lrow * KSTRIDE];

    for (int k0 = 0; k0 < K; k0 += 16) {
        float4 av0 = *(const float4*)&A[(size_t)(m0 + lrow) * K + k0 + lk];
        float4 av1 = *(const float4*)&A[(size_t)(m0 + lrow) * K + k0 + lk + 4];
        float4 bv0 = *(const float4*)&Bp[(size_t)(n0 + lrow) * K + k0 + lk];
        float4 bv1 = *(const float4*)&Bp[(size_t)(n0 + lrow) * K + k0 + lk + 4];
        if (a_gatt) {   // A from g_att (pointer swap done above; loads redone)
            av0 = *(const float4*)&A[(size_t)(m0 + lrow) * K + k0 + lk];
            av1 = *(const float4*)&A[(size_t)(m0 + lrow) * K + k0 + lk + 4];
        }
        __syncthreads();   // previous compute done before overwriting smem
        {
            const float ax[8] = {av0.x, av0.y, av0.z, av0.w,
                                 av1.x, av1.y, av1.z, av1.w};
            const float bx[8] = {bv0.x, bv0.y, bv0.z, bv0.w,
                                 bv1.x, bv1.y, bv1.z, bv1.w};
#pragma unroll
            for (int j = 0; j < 8; j++) {
                float xa = ax[j];
                __nv_bfloat16 ah = __float2bfloat16(xa);
                __nv_bfloat16 al = __float2bfloat16(xa - __bfloat162float(ah));
                Arow[lk + j]      = ah;   // seg0: hi
                Arow[16 + lk + j] = al;   // seg1: lo
                Arow[32 + lk + j] = ah;   // seg2: hi
                float xb = bx[j];
                __nv_bfloat16 bh = __float2bfloat16(xb);
                __nv_bfloat16 bl = __float2bfloat16(xb - __bfloat162float(bh));
                Brow[lk + j]      = bh;   // seg0: hi
                Brow[16 + lk + j] = bh;   // seg1: hi
                Brow[32 + lk + j] = bl;   // seg2: lo
            }
        }
        __syncthreads();

#pragma unroll
        for (int ks = 0; ks < 3; ks++) {
            const uint32_t kb = (uint32_t)(ks * 16) * 2u;   // bytes
            uint32_t bfr[4][2];
#pragma unroll
            for (int nt = 0; nt < 4; nt++)
                ldsm2(bfr[nt], b_base + kb + (uint32_t)(nt * 8 * KSTRIDE) * 2u);
#pragma unroll
            for (int mt = 0; mt < 4; mt++) {
                uint32_t afr[4];
                ldsm4(afr, a_base + kb + (uint32_t)(mt * 16 * KSTRIDE) * 2u);
#pragma unroll
                for (int nt = 0; nt < 4; nt++)
                    mma16816(acc[mt][nt], afr, bfr[nt]);
            }
        }
    }

    // Epilogue: lane holds C[g][c'],C[g][c'+1],C[g+8][c'],C[g+8][c'+1]
    const int g = lane >> 2, cc = (lane & 3) * 2;
#pragma unroll
    for (int mt = 0; mt < 4; mt++) {
#pragma unroll
        for (int nt = 0; nt < 4; nt++) {
            int row = m0 + wm * 64 + mt * 16 + g;
            int col = n0 + wn * 32 + nt * 8 + cc;
            float b0 = bias ? bias[col] : 0.f;
            float b1 = bias ? bias[col + 1] : 0.f;
            float2 v0 = make_float2(acc[mt][nt][0] + b0, acc[mt][nt][1] + b1);
            float2 v1 = make_float2(acc[mt][nt][2] + b0, acc[mt][nt][3] + b1);
            *(float2*)&C[(size_t)row * N + col] = v0;
            *(float2*)&C[(size_t)(row + 8) * N + col] = v1;
        }
    }
}

// ---------------------------------------------------------------------------
// RoPE apply (in-place on q,k sections of g_qkv). One block per row.
// ---------------------------------------------------------------------------
__global__ __launch_bounds__(256) void rope_kernel()
{
    __shared__ float s[2048];
    __shared__ float cs[32], sn[32];
    const int row = blockIdx.x;
    const int t = row & (TQ - 1);
    float* base = g_qkv + (size_t)row * D3;

    if (threadIdx.x < 32) {
        cs[threadIdx.x] = g_cos_tab[t * 32 + threadIdx.x];
        sn[threadIdx.x] = g_sin_tab[t * 32 + threadIdx.x];
    }
    for (int j = threadIdx.x; j < 2048; j += 256) s[j] = base[j];
    __syncthreads();
#pragma unroll
    for (int jj = 0; jj < 8; jj++) {
        int j = threadIdx.x + jj * 256;
        int i = j & (HD - 1);
        int hb = j - i;
        int f = i & 31;
        float self = s[j];
        float val;
        if (i < 32) val = self * cs[f] - s[hb + 2 * i + 1] * sn[f];
        else        val = self * cs[f] + s[hb + 2 * (i - 32)] * sn[f];
        base[j] = val;
    }
}

// ---------------------------------------------------------------------------
// Flash attention, fp32, STATIC shared (44.5 KB). Unchanged (at scalar peak;
// tensor conversion is next round's change).
// ---------------------------------------------------------------------------
__global__ __launch_bounds__(256) void flash_kernel()
{
    __shared__ float Qt[64][68];   // [d][qrow]
    __shared__ float Kt[64][36];   // [d][krow]
    __shared__ float Vs[32][68];   // [krow][d]
    __shared__ float Ps[64][36];   // [qrow][krow]

    const int bh = blockIdx.x;
    const int qt = blockIdx.y;
    const int b = bh >> 4, h = bh & 15;
    const float* Qg = g_qkv + (size_t)(b * TQ + qt * 64) * D3 + h * HD;
    const float* Kg = g_qkv + (size_t)(b * TQ) * D3 + DMODEL + h * HD;
    const float* Vg = Kg + DMODEL;

    const int tid = threadIdx.x;
    const int tx = tid & 15, ty = tid >> 4;
    const int tx2 = 2 * tx, tx4 = 4 * tx, ty4 = 4 * ty;

    for (int idx = tid; idx < 4096; idx += 256) {
        int r = idx >> 6, d = idx & 63;
        Qt[d][r] = Qg[(size_t)r * D3 + d];
    }

    float m[4], l[4], o[4][4];
#pragma unroll
    for (int r = 0; r < 4; r++) {
        m[r] = -1e30f; l[r] = 0.f;
#pragma unroll
        for (int c = 0; c < 4; c++) o[r][c] = 0.f;
    }

    for (int kt = 0; kt < 64; kt++) {
        __syncthreads();
        for (int idx = tid; idx < 2048; idx += 256) {
            int r = idx >> 6, d = idx & 63;
            size_t grow = (size_t)(kt * 32 + r) * D3 + d;
            Kt[d][r] = Kg[grow];
            Vs[r][d] = Vg[grow];
        }
        __syncthreads();

        float sacc[4][2];
#pragma unroll
        for (int r = 0; r < 4; r++) { sacc[r][0] = 0.f; sacc[r][1] = 0.f; }
#pragma unroll 8
        for (int k = 0; k < 64; k++) {
            float a0 = Qt[k][ty4 + 0], a1 = Qt[k][ty4 + 1];
            float a2 = Qt[k][ty4 + 2], a3 = Qt[k][ty4 + 3];
            float b0 = Kt[k][tx2 + 0], b1 = Kt[k][tx2 + 1];
            sacc[0][0] += a0 * b0; sacc[0][1] += a0 * b1;
            sacc[1][0] += a1 * b0; sacc[1][1] += a1 * b1;
            sacc[2][0] += a2 * b0; sacc[2][1] += a2 * b1;
            sacc[3][0] += a3 * b0; sacc[3][1] += a3 * b1;
        }

        float p[4][2];
#pragma unroll
        for (int r = 0; r < 4; r++) {
            sacc[r][0] *= 0.125f; sacc[r][1] *= 0.125f;
            float rm = fmaxf(sacc[r][0], sacc[r][1]);
            rm = fmaxf(rm, __shfl_xor_sync(0xffffffffu, rm, 8));
            rm = fmaxf(rm, __shfl_xor_sync(0xffffffffu, rm, 4));
            rm = fmaxf(rm, __shfl_xor_sync(0xffffffffu, rm, 2));
            rm = fmaxf(rm, __shfl_xor_sync(0xffffffffu, rm, 1));
            float mnew = fmaxf(m[r], rm);
            float corr = __expf(m[r] - mnew);
            p[r][0] = __expf(sacc[r][0] - mnew);
            p[r][1] = __expf(sacc[r][1] - mnew);
            float rs = p[r][0] + p[r][1];
            rs += __shfl_xor_sync(0xffffffffu, rs, 8);
            rs += __shfl_xor_sync(0xffffffffu, rs, 4);
            rs += __shfl_xor_sync(0xffffffffu, rs, 2);
            rs += __shfl_xor_sync(0xffffffffu, rs, 1);
            l[r] = l[r] * corr + rs;
            m[r] = mnew;
#pragma unroll
            for (int c = 0; c < 4; c++) o[r][c] *= corr;
        }

#pragma unroll
        for (int r = 0; r < 4; r++) {
            Ps[ty4 + r][tx2 + 0] = p[r][0];
            Ps[ty4 + r][tx2 + 1] = p[r][1];
        }
        __syncthreads();

#pragma unroll 8
        for (int k = 0; k < 32; k++) {
            float v0 = Vs[k][tx4 + 0], v1 = Vs[k][tx4 + 1];
            float v2 = Vs[k][tx4 + 2], v3 = Vs[k][tx4 + 3];
#pragma unroll
            for (int r = 0; r < 4; r++) {
                float pr = Ps[ty4 + r][k];
                o[r][0] += pr * v0; o[r][1] += pr * v1;
                o[r][2] += pr * v2; o[r][3] += pr * v3;
            }
        }
    }

#pragma unroll
    for (int r = 0; r < 4; r++) {
        float inv = 1.f / l[r];
        int trow = b * TQ + qt * 64 + ty4 + r;
        float4 v = make_float4(o[r][0] * inv, o[r][1] * inv,
                               o[r][2] * inv, o[r][3] * inv);
        *(float4*)&g_att[(size_t)trow * DMODEL + h * HD + tx4] = v;
    }
}

// ---------------------------------------------------------------------------
extern "C" void kernel_launch(void* const* d_in, const int* in_sizes, int n_in,
                              void* d_out, int out_size)
{
    // Identify inputs by unique element counts (robust to ordering).
    const float *x = 0, *w_qkv = 0, *w_out = 0, *b_out = 0;
    for (int i = 0; i < n_in; i++) {
        switch (in_sizes[i]) {
            case 4194304: x     = (const float*)d_in[i]; break;
            case 3145728: w_qkv = (const float*)d_in[i]; break;
            case 1048576: w_out = (const float*)d_in[i]; break;
            case 1024:    b_out = (const float*)d_in[i]; break;
        }
    }
    if (!x && n_in >= 4) {
        x     = (const float*)d_in[0];
        w_qkv = (const float*)d_in[1];
        w_out = (const float*)d_in[2];
        b_out = (const float*)d_in[3];
    }
    float* out = (float*)d_out;

    // 0) Pre-fills + RoPE tables.
    fill_qkv_kernel<<<4096, 256>>>();
    fill_att_kernel<<<2048, 256>>>();
    rope_table_kernel<<<(TQ * 32 + 255) / 256, 256>>>();
    // 1) g_qkv = x @ w_qkv^T   (4096 x 3072), bf16-split tensor GEMM
    gemm_nt_bf16x3<<<dim3(D3 / 128, BT / 128), 256>>>(
        x, w_qkv, nullptr, nullptr, BT, D3, DMODEL, 0, 1);
    // 2) RoPE in-place
    rope_kernel<<<BT, 256>>>();
    // 3) attention
    flash_kernel<<<dim3(32, 32), 256>>>();
    // 4) out = g_att @ w_out^T + b_out, bf16-split tensor GEMM
    gemm_nt_bf16x3<<<dim3(DMODEL / 128, BT / 128), 256>>>(
        nullptr, w_out, b_out, out, BT, DMODEL, DMODEL, 1, 0);
}

// round 8
// speedup vs baseline: 3.2510x; 1.8277x over previous
#include <cuda_runtime.h>
#include <cuda_bf16.h>
#include <math.h>
#include <stdint.h>

// Problem constants (B=2, T=2048, D=1024, H=16, hd=64)
#define BT 4096          // B*T rows
#define DMODEL 1024
#define D3 3072
#define NHEAD 16
#define HD 64
#define TQ 2048

// Scratch (device globals: runtime allocation is forbidden).
__device__ float g_qkv[(size_t)BT * D3];     // 48 MB
__device__ float g_att[(size_t)BT * DMODEL]; // 16 MB
__device__ float g_cos_tab[TQ * 32];         // 256 KB
__device__ float g_sin_tab[TQ * 32];         // 256 KB

// ---------------------------------------------------------------------------
// Pre-fills of scratch (kept from the first passing round).
// ---------------------------------------------------------------------------
__global__ __launch_bounds__(256) void fill_qkv_kernel()
{
    size_t n = (size_t)BT * D3;
    for (size_t i = blockIdx.x * 256ull + threadIdx.x; i < n;
         i += (size_t)gridDim.x * 256ull)
        g_qkv[i] = 0.05f;
}
__global__ __launch_bounds__(256) void fill_att_kernel()
{
    size_t n = (size_t)BT * DMODEL;
    for (size_t i = blockIdx.x * 256ull + threadIdx.x; i < n;
         i += (size_t)gridDim.x * 256ull)
        g_att[i] = 0.03f;
}

// ---------------------------------------------------------------------------
// RoPE tables: 2048 positions x 32 freqs (DP trig of fp32-rounded angle).
// ---------------------------------------------------------------------------
__global__ __launch_bounds__(256) void rope_table_kernel()
{
    int idx = blockIdx.x * 256 + threadIdx.x;   // 0..65535
    if (idx >= TQ * 32) return;
    int t = idx >> 5, f = idx & 31;
    float invf = (float)exp((double)f * (-9.210340371976184 / 32.0));
    float ang = (float)t * invf;                // fp32 product, like jax
    g_cos_tab[idx] = (float)cos((double)ang);
    g_sin_tab[idx] = (float)sin((double)ang);
}

// ---------------------------------------------------------------------------
// MMA helpers
// ---------------------------------------------------------------------------
__device__ __forceinline__ uint32_t sptr(const void* p)
{
    return (uint32_t)__cvta_generic_to_shared(p);
}
__device__ __forceinline__ void ldsm4(uint32_t* r, uint32_t addr)
{
    asm volatile("ldmatrix.sync.aligned.m8n8.x4.shared.b16 {%0,%1,%2,%3}, [%4];"
                 : "=r"(r[0]), "=r"(r[1]), "=r"(r[2]), "=r"(r[3]) : "r"(addr));
}
__device__ __forceinline__ void ldsm2(uint32_t* r, uint32_t addr)
{
    asm volatile("ldmatrix.sync.aligned.m8n8.x2.shared.b16 {%0,%1}, [%2];"
                 : "=r"(r[0]), "=r"(r[1]) : "r"(addr));
}
__device__ __forceinline__ void ldsm2t(uint32_t* r, uint32_t addr)
{
    asm volatile("ldmatrix.sync.aligned.m8n8.x2.trans.shared.b16 {%0,%1}, [%2];"
                 : "=r"(r[0]), "=r"(r[1]) : "r"(addr));
}
__device__ __forceinline__ void mma16816(float* c, const uint32_t* a,
                                         const uint32_t* b)
{
    asm volatile(
        "mma.sync.aligned.m16n8k16.row.col.f32.bf16.bf16.f32 "
        "{%0,%1,%2,%3}, {%4,%5,%6,%7}, {%8,%9}, {%0,%1,%2,%3};"
        : "+f"(c[0]), "+f"(c[1]), "+f"(c[2]), "+f"(c[3])
        : "r"(a[0]), "r"(a[1]), "r"(a[2]), "r"(a[3]), "r"(b[0]), "r"(b[1]));
}
// Pack two floats into bf16x2 hi and lo (residual) words.
__device__ __forceinline__ void pack_hl(float x, float y,
                                        uint32_t& hi, uint32_t& lo)
{
    __nv_bfloat16 xh = __float2bfloat16(x);
    __nv_bfloat16 yh = __float2bfloat16(y);
    __nv_bfloat162 h2 = {xh, yh};
    __nv_bfloat162 l2 = {__float2bfloat16(x - __bfloat162float(xh)),
                         __float2bfloat16(y - __bfloat162float(yh))};
    hi = *(uint32_t*)&h2;
    lo = *(uint32_t*)&l2;
}

// ---------------------------------------------------------------------------
// bf16-split tensor GEMM NT (unchanged from R7, passing).
// ---------------------------------------------------------------------------
#define KSTRIDE 56   // bf16 elems per smem row (48 + 8 pad); 112 B

__global__ __launch_bounds__(256, 2) void gemm_nt_bf16x3(
    const float* __restrict__ Ap, const float* __restrict__ Bp,
    const float* __restrict__ bias, float* __restrict__ Cp,
    int M, int N, int K, int a_gatt, int c_gqkv)
{
    const float* A = a_gatt ? (const float*)g_att : Ap;
    float* C = c_gqkv ? (float*)g_qkv : Cp;

    __shared__ __align__(16) __nv_bfloat16 As[128 * KSTRIDE];
    __shared__ __align__(16) __nv_bfloat16 Bs[128 * KSTRIDE];

    const int tid = threadIdx.x;
    const int lane = tid & 31, warp = tid >> 5;
    const int wm = warp >> 2, wn = warp & 3;
    const int m0 = blockIdx.y * 128, n0 = blockIdx.x * 128;

    const int lrow = tid >> 1;
    const int lk = (tid & 1) * 8;

    float acc[4][4][4];
#pragma unroll
    for (int mt = 0; mt < 4; mt++)
#pragma unroll
        for (int nt = 0; nt < 4; nt++)
#pragma unroll
            for (int i = 0; i < 4; i++) acc[mt][nt][i] = 0.f;

    const int a_row = wm * 64 + (lane & 15);
    const int a_kof = (lane >> 4) * 8;
    uint32_t a_base = sptr(As) + (uint32_t)(a_row * KSTRIDE + a_kof) * 2u;
    const int b_row = wn * 32 + (lane & 7);
    const int b_kof = ((lane & 15) >> 3) * 8;
    uint32_t b_base = sptr(Bs) + (uint32_t)(b_row * KSTRIDE + b_kof) * 2u;

    __nv_bfloat16* Arow = &As[lrow * KSTRIDE];
    __nv_bfloat16* Brow = &Bs[lrow * KSTRIDE];

    for (int k0 = 0; k0 < K; k0 += 16) {
        float4 av0 = *(const float4*)&A[(size_t)(m0 + lrow) * K + k0 + lk];
        float4 av1 = *(const float4*)&A[(size_t)(m0 + lrow) * K + k0 + lk + 4];
        float4 bv0 = *(const float4*)&Bp[(size_t)(n0 + lrow) * K + k0 + lk];
        float4 bv1 = *(const float4*)&Bp[(size_t)(n0 + lrow) * K + k0 + lk + 4];
        __syncthreads();
        {
            const float ax[8] = {av0.x, av0.y, av0.z, av0.w,
                                 av1.x, av1.y, av1.z, av1.w};
            const float bx[8] = {bv0.x, bv0.y, bv0.z, bv0.w,
                                 bv1.x, bv1.y, bv1.z, bv1.w};
#pragma unroll
            for (int j = 0; j < 8; j++) {
                float xa = ax[j];
                __nv_bfloat16 ah = __float2bfloat16(xa);
                __nv_bfloat16 al = __float2bfloat16(xa - __bfloat162float(ah));
                Arow[lk + j]      = ah;
                Arow[16 + lk + j] = al;
                Arow[32 + lk + j] = ah;
                float xb = bx[j];
                __nv_bfloat16 bh = __float2bfloat16(xb);
                __nv_bfloat16 bl = __float2bfloat16(xb - __bfloat162float(bh));
                Brow[lk + j]      = bh;
                Brow[16 + lk + j] = bh;
                Brow[32 + lk + j] = bl;
            }
        }
        __syncthreads();

#pragma unroll
        for (int ks = 0; ks < 3; ks++) {
            const uint32_t kb = (uint32_t)(ks * 16) * 2u;
            uint32_t bfr[4][2];
#pragma unroll
            for (int nt = 0; nt < 4; nt++)
                ldsm2(bfr[nt], b_base + kb + (uint32_t)(nt * 8 * KSTRIDE) * 2u);
#pragma unroll
            for (int mt = 0; mt < 4; mt++) {
                uint32_t afr[4];
                ldsm4(afr, a_base + kb + (uint32_t)(mt * 16 * KSTRIDE) * 2u);
#pragma unroll
                for (int nt = 0; nt < 4; nt++)
                    mma16816(acc[mt][nt], afr, bfr[nt]);
            }
        }
    }

    const int g = lane >> 2, cc = (lane & 3) * 2;
#pragma unroll
    for (int mt = 0; mt < 4; mt++) {
#pragma unroll
        for (int nt = 0; nt < 4; nt++) {
            int row = m0 + wm * 64 + mt * 16 + g;
            int col = n0 + wn * 32 + nt * 8 + cc;
            float b0 = bias ? bias[col] : 0.f;
            float b1 = bias ? bias[col + 1] : 0.f;
            float2 v0 = make_float2(acc[mt][nt][0] + b0, acc[mt][nt][1] + b1);
            float2 v1 = make_float2(acc[mt][nt][2] + b0, acc[mt][nt][3] + b1);
            *(float2*)&C[(size_t)row * N + col] = v0;
            *(float2*)&C[(size_t)(row + 8) * N + col] = v1;
        }
    }
}

// ---------------------------------------------------------------------------
// RoPE apply (in-place on q,k sections of g_qkv). One block per row.
// ---------------------------------------------------------------------------
__global__ __launch_bounds__(256) void rope_kernel()
{
    __shared__ float s[2048];
    __shared__ float cs[32], sn[32];
    const int row = blockIdx.x;
    const int t = row & (TQ - 1);
    float* base = g_qkv + (size_t)row * D3;

    if (threadIdx.x < 32) {
        cs[threadIdx.x] = g_cos_tab[t * 32 + threadIdx.x];
        sn[threadIdx.x] = g_sin_tab[t * 32 + threadIdx.x];
    }
    for (int j = threadIdx.x; j < 2048; j += 256) s[j] = base[j];
    __syncthreads();
#pragma unroll
    for (int jj = 0; jj < 8; jj++) {
        int j = threadIdx.x + jj * 256;
        int i = j & (HD - 1);
        int hb = j - i;
        int f = i & 31;
        float self = s[j];
        float val;
        if (i < 32) val = self * cs[f] - s[hb + 2 * i + 1] * sn[f];
        else        val = self * cs[f] + s[hb + 2 * (i - 32)] * sn[f];
        base[j] = val;
    }
}

// ---------------------------------------------------------------------------
// Tensor-core flash attention (bf16x3 split, fp32 softmax/accum).
// CTA = (batch*head, 64-q-tile), 128 threads / 4 warps; warp owns 16 q rows.
// KV tile 64. S = Qh*Kh + Ql*Kh + Qh*Kl (scale 1/8 folded into Q split).
// P kept in registers; PV = Ph*Vh + Pl*Vh + Ph*Vl with V via ldmatrix.trans.
// Smem 36 KB static: Khi|Klo|Vhi|Vlo (Q staged in Khi/Klo before the loop).
// ---------------------------------------------------------------------------
#define FKST 72   // bf16 elems per smem row (64 + 8 pad) = 144 B

__global__ __launch_bounds__(128) void flash_tc_kernel()
{
    __shared__ __align__(16) char sm_raw[4 * 64 * FKST * 2];  // 36864 B
    __nv_bfloat16* KH = (__nv_bfloat16*)(sm_raw);
    __nv_bfloat16* KL = (__nv_bfloat16*)(sm_raw + 9216);
    __nv_bfloat16* VH = (__nv_bfloat16*)(sm_raw + 18432);
    __nv_bfloat16* VL = (__nv_bfloat16*)(sm_raw + 27648);

    const int bh = blockIdx.x, qt = blockIdx.y;
    const int b = bh >> 4, h = bh & 15;
    const float* Qg = g_qkv + (size_t)(b * TQ + qt * 64) * D3 + h * HD;
    const float* Kg = g_qkv + (size_t)(b * TQ) * D3 + DMODEL + h * HD;
    const float* Vg = Kg + DMODEL;

    const int tid = threadIdx.x, lane = tid & 31, warp = tid >> 5;

    // ---- Stage Q (scaled by 1/8, split hi/lo) into KH/KL, grab frags ----
    for (int f = tid; f < 1024; f += 128) {
        int r = f >> 4, c = (f & 15) * 4;
        float4 v = *(const float4*)&Qg[(size_t)r * D3 + c];
        float a[4] = {v.x, v.y, v.z, v.w};
#pragma unroll
        for (int j = 0; j < 4; j++) {
            float x = a[j] * 0.125f;
            __nv_bfloat16 hi = __float2bfloat16(x);
            KH[r * FKST + c + j] = hi;
            KL[r * FKST + c + j] = __float2bfloat16(x - __bfloat162float(hi));
        }
    }
    __syncthreads();

    uint32_t qh[4][4], ql[4][4];
    {
        int arow = warp * 16 + (lane & 15);
        int akof = (lane >> 4) * 8;
        uint32_t qa = sptr(KH) + (uint32_t)(arow * FKST + akof) * 2u;
#pragma unroll
        for (int ks = 0; ks < 4; ks++) {
            ldsm4(qh[ks], qa + ks * 32);
            ldsm4(ql[ks], qa + ks * 32 + 9216);
        }
    }
    __syncthreads();

    // ldmatrix bases for K (non-trans) and V (trans)
    uint32_t kfb = sptr(KH) +
        (uint32_t)((lane & 7) * FKST + (((lane >> 3) & 1) * 8)) * 2u;
    uint32_t vfb = sptr(VH) + (uint32_t)((lane & 15) * FKST) * 2u;

    float m0 = -1e30f, m1 = -1e30f, l0 = 0.f, l1 = 0.f;
    float oacc[8][4];
#pragma unroll
    for (int nt = 0; nt < 8; nt++)
#pragma unroll
        for (int i = 0; i < 4; i++) oacc[nt][i] = 0.f;

    for (int kt = 0; kt < 32; kt++) {
        __syncthreads();
        // Load + convert K,V tile (64 x 64)
        for (int f = tid; f < 1024; f += 128) {
            int r = f >> 4, c = (f & 15) * 4;
            size_t go = (size_t)(kt * 64 + r) * D3 + c;
            float4 kv = *(const float4*)&Kg[go];
            float4 vv = *(const float4*)&Vg[go];
            float ka[4] = {kv.x, kv.y, kv.z, kv.w};
            float va[4] = {vv.x, vv.y, vv.z, vv.w};
#pragma unroll
            for (int j = 0; j < 4; j++) {
                __nv_bfloat16 khi = __float2bfloat16(ka[j]);
                KH[r * FKST + c + j] = khi;
                KL[r * FKST + c + j] =
                    __float2bfloat16(ka[j] - __bfloat162float(khi));
                __nv_bfloat16 vhi = __float2bfloat16(va[j]);
                VH[r * FKST + c + j] = vhi;
                VL[r * FKST + c + j] =
                    __float2bfloat16(va[j] - __bfloat162float(vhi));
            }
        }
        __syncthreads();

        // ---- S = Q K^T (scaled) ----
        float sacc[8][4];
#pragma unroll
        for (int nt = 0; nt < 8; nt++)
#pragma unroll
            for (int i = 0; i < 4; i++) sacc[nt][i] = 0.f;
#pragma unroll
        for (int ks = 0; ks < 4; ks++) {
#pragma unroll
            for (int nt = 0; nt < 8; nt++) {
                uint32_t ad = kfb + (uint32_t)(nt * 8 * FKST) * 2u + ks * 32;
                uint32_t bh2[2], bl2[2];
                ldsm2(bh2, ad);
                ldsm2(bl2, ad + 9216);
                mma16816(sacc[nt], qh[ks], bh2);
                mma16816(sacc[nt], ql[ks], bh2);
                mma16816(sacc[nt], qh[ks], bl2);
            }
        }

        // ---- online softmax (rows g=lane>>2 and g+8, warp-local) ----
        float rm0 = -1e30f, rm1 = -1e30f;
#pragma unroll
        for (int nt = 0; nt < 8; nt++) {
            rm0 = fmaxf(rm0, fmaxf(sacc[nt][0], sacc[nt][1]));
            rm1 = fmaxf(rm1, fmaxf(sacc[nt][2], sacc[nt][3]));
        }
        rm0 = fmaxf(rm0, __shfl_xor_sync(0xffffffffu, rm0, 1));
        rm0 = fmaxf(rm0, __shfl_xor_sync(0xffffffffu, rm0, 2));
        rm1 = fmaxf(rm1, __shfl_xor_sync(0xffffffffu, rm1, 1));
        rm1 = fmaxf(rm1, __shfl_xor_sync(0xffffffffu, rm1, 2));
        float mn0 = fmaxf(m0, rm0), mn1 = fmaxf(m1, rm1);
        float c0 = __expf(m0 - mn0), c1 = __expf(m1 - mn1);
        float p[8][4];
        float s0 = 0.f, s1 = 0.f;
#pragma unroll
        for (int nt = 0; nt < 8; nt++) {
            p[nt][0] = __expf(sacc[nt][0] - mn0);
            p[nt][1] = __expf(sacc[nt][1] - mn0);
            p[nt][2] = __expf(sacc[nt][2] - mn1);
            p[nt][3] = __expf(sacc[nt][3] - mn1);
            s0 += p[nt][0] + p[nt][1];
            s1 += p[nt][2] + p[nt][3];
        }
        s0 += __shfl_xor_sync(0xffffffffu, s0, 1);
        s0 += __shfl_xor_sync(0xffffffffu, s0, 2);
        s1 += __shfl_xor_sync(0xffffffffu, s1, 1);
        s1 += __shfl_xor_sync(0xffffffffu, s1, 2);
        l0 = l0 * c0 + s0; l1 = l1 * c1 + s1;
        m0 = mn0; m1 = mn1;
#pragma unroll
        for (int nt = 0; nt < 8; nt++) {
            oacc[nt][0] *= c0; oacc[nt][1] *= c0;
            oacc[nt][2] *= c1; oacc[nt][3] *= c1;
        }

        // ---- O += P V ----
#pragma unroll
        for (int j = 0; j < 4; j++) {        // k16 block = S tiles 2j, 2j+1
            uint32_t ph[4], pl[4];
            pack_hl(p[2 * j][0],     p[2 * j][1],     ph[0], pl[0]);
            pack_hl(p[2 * j][2],     p[2 * j][3],     ph[1], pl[1]);
            pack_hl(p[2 * j + 1][0], p[2 * j + 1][1], ph[2], pl[2]);
            pack_hl(p[2 * j + 1][2], p[2 * j + 1][3], ph[3], pl[3]);
#pragma unroll
            for (int nt = 0; nt < 8; nt++) {
                uint32_t ad = vfb + (uint32_t)(j * 16 * FKST) * 2u + nt * 16;
                uint32_t vh2[2], vl2[2];
                ldsm2t(vh2, ad);
                ldsm2t(vl2, ad + 9216);
                mma16816(oacc[nt], ph, vh2);
                mma16816(oacc[nt], pl, vh2);
                mma16816(oacc[nt], ph, vl2);
            }
        }
    }

    // ---- epilogue ----
    float il0 = 1.f / l0, il1 = 1.f / l1;
    int g = lane >> 2, cc2 = (lane & 3) * 2;
    int row0 = b * TQ + qt * 64 + warp * 16 + g;
#pragma unroll
    for (int nt = 0; nt < 8; nt++) {
        int col = h * HD + nt * 8 + cc2;
        float2 v0 = make_float2(oacc[nt][0] * il0, oacc[nt][1] * il0);
        float2 v1 = make_float2(oacc[nt][2] * il1, oacc[nt][3] * il1);
        *(float2*)&g_att[(size_t)row0 * DMODEL + col] = v0;
        *(float2*)&g_att[(size_t)(row0 + 8) * DMODEL + col] = v1;
    }
}

// ---------------------------------------------------------------------------
extern "C" void kernel_launch(void* const* d_in, const int* in_sizes, int n_in,
                              void* d_out, int out_size)
{
    const float *x = 0, *w_qkv = 0, *w_out = 0, *b_out = 0;
    for (int i = 0; i < n_in; i++) {
        switch (in_sizes[i]) {
            case 4194304: x     = (const float*)d_in[i]; break;
            case 3145728: w_qkv = (const float*)d_in[i]; break;
            case 1048576: w_out = (const float*)d_in[i]; break;
            case 1024:    b_out = (const float*)d_in[i]; break;
        }
    }
    if (!x && n_in >= 4) {
        x     = (const float*)d_in[0];
        w_qkv = (const float*)d_in[1];
        w_out = (const float*)d_in[2];
        b_out = (const float*)d_in[3];
    }
    float* out = (float*)d_out;

    fill_qkv_kernel<<<4096, 256>>>();
    fill_att_kernel<<<2048, 256>>>();
    rope_table_kernel<<<(TQ * 32 + 255) / 256, 256>>>();
    gemm_nt_bf16x3<<<dim3(D3 / 128, BT / 128), 256>>>(
        x, w_qkv, nullptr, nullptr, BT, D3, DMODEL, 0, 1);
    rope_kernel<<<BT, 256>>>();
    flash_tc_kernel<<<dim3(32, 32), 128>>>();
    gemm_nt_bf16x3<<<dim3(DMODEL / 128, BT / 128), 256>>>(
        nullptr, w_out, b_out, out, BT, DMODEL, DMODEL, 1, 0);
}

// round 9
// speedup vs baseline: 3.4583x; 1.0638x over previous
#include <cuda_runtime.h>
#include <cuda_bf16.h>
#include <math.h>
#include <stdint.h>

// Problem constants (B=2, T=2048, D=1024, H=16, hd=64)
#define BT 4096          // B*T rows
#define DMODEL 1024
#define D3 3072
#define NHEAD 16
#define HD 64
#define TQ 2048

// Scratch (device globals: runtime allocation is forbidden).
__device__ float g_qkv[(size_t)BT * D3];     // 48 MB
__device__ float g_att[(size_t)BT * DMODEL]; // 16 MB
__device__ float g_cos_tab[TQ * 32];         // 256 KB
__device__ float g_sin_tab[TQ * 32];         // 256 KB

// ---------------------------------------------------------------------------
// Pre-fills of scratch (kept from the first passing round).
// ---------------------------------------------------------------------------
__global__ __launch_bounds__(256) void fill_qkv_kernel()
{
    size_t n = (size_t)BT * D3;
    for (size_t i = blockIdx.x * 256ull + threadIdx.x; i < n;
         i += (size_t)gridDim.x * 256ull)
        g_qkv[i] = 0.05f;
}
__global__ __launch_bounds__(256) void fill_att_kernel()
{
    size_t n = (size_t)BT * DMODEL;
    for (size_t i = blockIdx.x * 256ull + threadIdx.x; i < n;
         i += (size_t)gridDim.x * 256ull)
        g_att[i] = 0.03f;
}

// ---------------------------------------------------------------------------
// RoPE tables: 2048 positions x 32 freqs (DP trig of fp32-rounded angle).
// ---------------------------------------------------------------------------
__global__ __launch_bounds__(256) void rope_table_kernel()
{
    int idx = blockIdx.x * 256 + threadIdx.x;   // 0..65535
    if (idx >= TQ * 32) return;
    int t = idx >> 5, f = idx & 31;
    float invf = (float)exp((double)f * (-9.210340371976184 / 32.0));
    float ang = (float)t * invf;                // fp32 product, like jax
    g_cos_tab[idx] = (float)cos((double)ang);
    g_sin_tab[idx] = (float)sin((double)ang);
}

// ---------------------------------------------------------------------------
// MMA helpers
// ---------------------------------------------------------------------------
__device__ __forceinline__ uint32_t sptr(const void* p)
{
    return (uint32_t)__cvta_generic_to_shared(p);
}
__device__ __forceinline__ void ldsm4(uint32_t* r, uint32_t addr)
{
    asm volatile("ldmatrix.sync.aligned.m8n8.x4.shared.b16 {%0,%1,%2,%3}, [%4];"
                 : "=r"(r[0]), "=r"(r[1]), "=r"(r[2]), "=r"(r[3]) : "r"(addr));
}
__device__ __forceinline__ void ldsm4t(uint32_t* r, uint32_t addr)
{
    asm volatile("ldmatrix.sync.aligned.m8n8.x4.trans.shared.b16 {%0,%1,%2,%3}, [%4];"
                 : "=r"(r[0]), "=r"(r[1]), "=r"(r[2]), "=r"(r[3]) : "r"(addr));
}
__device__ __forceinline__ void mma16816(float* c, const uint32_t* a,
                                         const uint32_t* b)
{
    asm volatile(
        "mma.sync.aligned.m16n8k16.row.col.f32.bf16.bf16.f32 "
        "{%0,%1,%2,%3}, {%4,%5,%6,%7}, {%8,%9}, {%0,%1,%2,%3};"
        : "+f"(c[0]), "+f"(c[1]), "+f"(c[2]), "+f"(c[3])
        : "r"(a[0]), "r"(a[1]), "r"(a[2]), "r"(a[3]), "r"(b[0]), "r"(b[1]));
}
// Pack two floats into bf16x2 hi and lo (residual) words.
__device__ __forceinline__ void pack_hl(float x, float y,
                                        uint32_t& hi, uint32_t& lo)
{
    __nv_bfloat16 xh = __float2bfloat16(x);
    __nv_bfloat16 yh = __float2bfloat16(y);
    __nv_bfloat162 h2 = {xh, yh};
    __nv_bfloat162 l2 = {__float2bfloat16(x - __bfloat162float(xh)),
                         __float2bfloat16(y - __bfloat162float(yh))};
    hi = *(uint32_t*)&h2;
    lo = *(uint32_t*)&l2;
}

// ---------------------------------------------------------------------------
// bf16-split tensor GEMM NT: C = A @ B^T (+bias), dedup [hi|lo] smem layout.
// CTA 128x128, BK=16 fp32 (32 bf16 stored), 8 warps (2x4), warp tile 64x32.
// 3 products from register fragments: Ah*Bh + Al*Bh + Ah*Bl.
// Smem 20 KB static. a_gatt: A = g_att. c_gqkv: C = g_qkv.
// ---------------------------------------------------------------------------
#define KST2 40   // bf16 elems per smem row (32 data + 8 pad) = 80 B

__global__ __launch_bounds__(256, 2) void gemm_nt_bf16x3(
    const float* __restrict__ Ap, const float* __restrict__ Bp,
    const float* __restrict__ bias, float* __restrict__ Cp,
    int M, int N, int K, int a_gatt, int c_gqkv)
{
    const float* A = a_gatt ? (const float*)g_att : Ap;
    float* C = c_gqkv ? (float*)g_qkv : Cp;

    __shared__ __align__(16) __nv_bfloat16 As[128 * KST2];
    __shared__ __align__(16) __nv_bfloat16 Bs[128 * KST2];

    const int tid = threadIdx.x;
    const int lane = tid & 31, warp = tid >> 5;
    const int wm = warp >> 2, wn = warp & 3;   // 2 x 4 warp grid
    const int m0 = blockIdx.y * 128, n0 = blockIdx.x * 128;

    const int lrow = tid >> 1;          // 0..127
    const int lk = (tid & 1) * 8;       // 0 or 8

    float acc[4][4][4];
#pragma unroll
    for (int mt = 0; mt < 4; mt++)
#pragma unroll
        for (int nt = 0; nt < 4; nt++)
#pragma unroll
            for (int i = 0; i < 4; i++) acc[mt][nt][i] = 0.f;

    // A frag address: rows wm*64 + (lane&15), k elems (lane>>4)*8 (hi seg).
    const int a_row = wm * 64 + (lane & 15);
    uint32_t a_base = sptr(As) +
        (uint32_t)(a_row * KST2 + (lane >> 4) * 8) * 2u;
    // B frag address (x4, nt-pair folded): rows wn*32 + (lane&7) +
    // ((lane>>4)&1)*8, k elems ((lane>>3)&1)*8.
    const int b_row = wn * 32 + (lane & 7) + ((lane >> 4) & 1) * 8;
    uint32_t b_base = sptr(Bs) +
        (uint32_t)(b_row * KST2 + ((lane >> 3) & 1) * 8) * 2u;

    uint32_t* Arow32 = (uint32_t*)&As[lrow * KST2];
    uint32_t* Brow32 = (uint32_t*)&Bs[lrow * KST2];
    const int sidx = lk >> 1;           // uint32 index of hi block

    for (int k0 = 0; k0 < K; k0 += 16) {
        float4 av0 = *(const float4*)&A[(size_t)(m0 + lrow) * K + k0 + lk];
        float4 av1 = *(const float4*)&A[(size_t)(m0 + lrow) * K + k0 + lk + 4];
        float4 bv0 = *(const float4*)&Bp[(size_t)(n0 + lrow) * K + k0 + lk];
        float4 bv1 = *(const float4*)&Bp[(size_t)(n0 + lrow) * K + k0 + lk + 4];
        __syncthreads();   // previous compute done before overwriting smem
        {
            uint32_t h, l;
            pack_hl(av0.x, av0.y, h, l); Arow32[sidx+0] = h; Arow32[8+sidx+0] = l;
            pack_hl(av0.z, av0.w, h, l); Arow32[sidx+1] = h; Arow32[8+sidx+1] = l;
            pack_hl(av1.x, av1.y, h, l); Arow32[sidx+2] = h; Arow32[8+sidx+2] = l;
            pack_hl(av1.z, av1.w, h, l); Arow32[sidx+3] = h; Arow32[8+sidx+3] = l;
            pack_hl(bv0.x, bv0.y, h, l); Brow32[sidx+0] = h; Brow32[8+sidx+0] = l;
            pack_hl(bv0.z, bv0.w, h, l); Brow32[sidx+1] = h; Brow32[8+sidx+1] = l;
            pack_hl(bv1.x, bv1.y, h, l); Brow32[sidx+2] = h; Brow32[8+sidx+2] = l;
            pack_hl(bv1.z, bv1.w, h, l); Brow32[sidx+3] = h; Brow32[8+sidx+3] = l;
        }
        __syncthreads();

        // B fragments: 2 x ldsm4 per (hi/lo), covering all 4 nt.
        uint32_t bh[4][2], bl[4][2];
#pragma unroll
        for (int ntp = 0; ntp < 2; ntp++) {
            uint32_t ad = b_base + (uint32_t)(ntp * 16 * KST2) * 2u;
            uint32_t t4[4];
            ldsm4(t4, ad);            // hi
            bh[2*ntp][0] = t4[0]; bh[2*ntp][1] = t4[1];
            bh[2*ntp+1][0] = t4[2]; bh[2*ntp+1][1] = t4[3];
            ldsm4(t4, ad + 32);       // lo (elems 16..31)
            bl[2*ntp][0] = t4[0]; bl[2*ntp][1] = t4[1];
            bl[2*ntp+1][0] = t4[2]; bl[2*ntp+1][1] = t4[3];
        }
#pragma unroll
        for (int mt = 0; mt < 4; mt++) {
            uint32_t ah[4], al[4];
            uint32_t ad = a_base + (uint32_t)(mt * 16 * KST2) * 2u;
            ldsm4(ah, ad);
            ldsm4(al, ad + 32);
#pragma unroll
            for (int nt = 0; nt < 4; nt++) {
                mma16816(acc[mt][nt], ah, bh[nt]);
                mma16816(acc[mt][nt], al, bh[nt]);
                mma16816(acc[mt][nt], ah, bl[nt]);
            }
        }
    }

    const int g = lane >> 2, cc = (lane & 3) * 2;
#pragma unroll
    for (int mt = 0; mt < 4; mt++) {
#pragma unroll
        for (int nt = 0; nt < 4; nt++) {
            int row = m0 + wm * 64 + mt * 16 + g;
            int col = n0 + wn * 32 + nt * 8 + cc;
            float b0 = bias ? bias[col] : 0.f;
            float b1 = bias ? bias[col + 1] : 0.f;
            float2 v0 = make_float2(acc[mt][nt][0] + b0, acc[mt][nt][1] + b1);
            float2 v1 = make_float2(acc[mt][nt][2] + b0, acc[mt][nt][3] + b1);
            *(float2*)&C[(size_t)row * N + col] = v0;
            *(float2*)&C[(size_t)(row + 8) * N + col] = v1;
        }
    }
}

// ---------------------------------------------------------------------------
// RoPE apply (in-place on q,k sections of g_qkv). One block per row.
// ---------------------------------------------------------------------------
__global__ __launch_bounds__(256) void rope_kernel()
{
    __shared__ float s[2048];
    __shared__ float cs[32], sn[32];
    const int row = blockIdx.x;
    const int t = row & (TQ - 1);
    float* base = g_qkv + (size_t)row * D3;

    if (threadIdx.x < 32) {
        cs[threadIdx.x] = g_cos_tab[t * 32 + threadIdx.x];
        sn[threadIdx.x] = g_sin_tab[t * 32 + threadIdx.x];
    }
    for (int j = threadIdx.x; j < 2048; j += 256) s[j] = base[j];
    __syncthreads();
#pragma unroll
    for (int jj = 0; jj < 8; jj++) {
        int j = threadIdx.x + jj * 256;
        int i = j & (HD - 1);
        int hb = j - i;
        int f = i & 31;
        float self = s[j];
        float val;
        if (i < 32) val = self * cs[f] - s[hb + 2 * i + 1] * sn[f];
        else        val = self * cs[f] + s[hb + 2 * (i - 32)] * sn[f];
        base[j] = val;
    }
}

// ---------------------------------------------------------------------------
// Tensor-core flash attention (bf16x3 split, fp32 softmax/accum).
// CTA = (batch*head, 64-q-tile), 128 threads / 4 warps; warp owns 16 q rows.
// KV tile 64. S = Qh*Kh + Ql*Kh + Qh*Kl (scale 1/8 folded into Q split).
// P in registers; PV = Ph*Vh + Pl*Vh + Ph*Vl, V via ldmatrix.x4.trans.
// Smem 36 KB static: Khi|Klo|Vhi|Vlo (Q staged in Khi/Klo before the loop).
// ---------------------------------------------------------------------------
#define FKST 72   // bf16 elems per smem row (64 + 8 pad) = 144 B

__global__ __launch_bounds__(128) void flash_tc_kernel()
{
    __shared__ __align__(16) char sm_raw[4 * 64 * FKST * 2];  // 36864 B
    __nv_bfloat16* KH = (__nv_bfloat16*)(sm_raw);
    __nv_bfloat16* KL = (__nv_bfloat16*)(sm_raw + 9216);
    __nv_bfloat16* VH = (__nv_bfloat16*)(sm_raw + 18432);
    __nv_bfloat16* VL = (__nv_bfloat16*)(sm_raw + 27648);

    const int bh = blockIdx.x, qt = blockIdx.y;
    const int b = bh >> 4, h = bh & 15;
    const float* Qg = g_qkv + (size_t)(b * TQ + qt * 64) * D3 + h * HD;
    const float* Kg = g_qkv + (size_t)(b * TQ) * D3 + DMODEL + h * HD;
    const float* Vg = Kg + DMODEL;

    const int tid = threadIdx.x, lane = tid & 31, warp = tid >> 5;

    // ---- Stage Q (scaled by 1/8, split hi/lo) into KH/KL, grab frags ----
    for (int f = tid; f < 1024; f += 128) {
        int r = f >> 4, c = (f & 15) * 4;
        float4 v = *(const float4*)&Qg[(size_t)r * D3 + c];
        uint32_t h0, l0, h1, l1;
        pack_hl(v.x * 0.125f, v.y * 0.125f, h0, l0);
        pack_hl(v.z * 0.125f, v.w * 0.125f, h1, l1);
        uint32_t* KHr = (uint32_t*)&KH[r * FKST];
        uint32_t* KLr = (uint32_t*)&KL[r * FKST];
        KHr[(c >> 1)] = h0; KHr[(c >> 1) + 1] = h1;
        KLr[(c >> 1)] = l0; KLr[(c >> 1) + 1] = l1;
    }
    __syncthreads();

    uint32_t qh[4][4], ql[4][4];
    {
        int arow = warp * 16 + (lane & 15);
        int akof = (lane >> 4) * 8;
        uint32_t qa = sptr(KH) + (uint32_t)(arow * FKST + akof) * 2u;
#pragma unroll
        for (int ks = 0; ks < 4; ks++) {
            ldsm4(qh[ks], qa + ks * 32);
            ldsm4(ql[ks], qa + ks * 32 + 9216);
        }
    }
    __syncthreads();

    // K frag base (x4, nt-pair folded): rows (lane&7) + ((lane>>4)&1)*8,
    // d elems ((lane>>3)&1)*8.
    uint32_t kfb = sptr(KH) +
        (uint32_t)(((lane & 7) + ((lane >> 4) & 1) * 8) * FKST +
                   ((lane >> 3) & 1) * 8) * 2u;
    // V frag base (x4 trans, nt-pair folded): rows lane&15, col byte
    // offset ((lane>>4)&1)*16.
    uint32_t vfb = sptr(VH) + (uint32_t)((lane & 15) * FKST) * 2u +
                   ((lane >> 4) & 1) * 16u;

    float m0 = -1e30f, m1 = -1e30f, l0 = 0.f, l1 = 0.f;
    float oacc[8][4];
#pragma unroll
    for (int nt = 0; nt < 8; nt++)
#pragma unroll
        for (int i = 0; i < 4; i++) oacc[nt][i] = 0.f;

    for (int kt = 0; kt < 32; kt++) {
        __syncthreads();
        // Load + convert K,V tile (64 x 64), packed hi/lo stores.
        for (int f = tid; f < 1024; f += 128) {
            int r = f >> 4, c = (f & 15) * 4;
            size_t go = (size_t)(kt * 64 + r) * D3 + c;
            float4 kv = *(const float4*)&Kg[go];
            float4 vv = *(const float4*)&Vg[go];
            uint32_t h0, lo0, h1, lo1;
            pack_hl(kv.x, kv.y, h0, lo0);
            pack_hl(kv.z, kv.w, h1, lo1);
            uint32_t* KHr = (uint32_t*)&KH[r * FKST];
            uint32_t* KLr = (uint32_t*)&KL[r * FKST];
            KHr[(c >> 1)] = h0; KHr[(c >> 1) + 1] = h1;
            KLr[(c >> 1)] = lo0; KLr[(c >> 1) + 1] = lo1;
            pack_hl(vv.x, vv.y, h0, lo0);
            pack_hl(vv.z, vv.w, h1, lo1);
            uint32_t* VHr = (uint32_t*)&VH[r * FKST];
            uint32_t* VLr = (uint32_t*)&VL[r * FKST];
            VHr[(c >> 1)] = h0; VHr[(c >> 1) + 1] = h1;
            VLr[(c >> 1)] = lo0; VLr[(c >> 1) + 1] = lo1;
        }
        __syncthreads();

        // ---- S = Q K^T (scaled) ----
        float sacc[8][4];
#pragma unroll
        for (int nt = 0; nt < 8; nt++)
#pragma unroll
            for (int i = 0; i < 4; i++) sacc[nt][i] = 0.f;
#pragma unroll
        for (int ks = 0; ks < 4; ks++) {
#pragma unroll
            for (int ntp = 0; ntp < 4; ntp++) {
                uint32_t ad = kfb + (uint32_t)(ntp * 16 * FKST) * 2u + ks * 32;
                uint32_t bh4[4], bl4[4];
                ldsm4(bh4, ad);
                ldsm4(bl4, ad + 9216);
                mma16816(sacc[2*ntp],   qh[ks], bh4);
                mma16816(sacc[2*ntp],   ql[ks], bh4);
                mma16816(sacc[2*ntp],   qh[ks], bl4);
                mma16816(sacc[2*ntp+1], qh[ks], bh4 + 2);
                mma16816(sacc[2*ntp+1], ql[ks], bh4 + 2);
                mma16816(sacc[2*ntp+1], qh[ks], bl4 + 2);
            }
        }

        // ---- online softmax (rows g=lane>>2 and g+8, warp-local) ----
        float rm0 = -1e30f, rm1 = -1e30f;
#pragma unroll
        for (int nt = 0; nt < 8; nt++) {
            rm0 = fmaxf(rm0, fmaxf(sacc[nt][0], sacc[nt][1]));
            rm1 = fmaxf(rm1, fmaxf(sacc[nt][2], sacc[nt][3]));
        }
        rm0 = fmaxf(rm0, __shfl_xor_sync(0xffffffffu, rm0, 1));
        rm0 = fmaxf(rm0, __shfl_xor_sync(0xffffffffu, rm0, 2));
        rm1 = fmaxf(rm1, __shfl_xor_sync(0xffffffffu, rm1, 1));
        rm1 = fmaxf(rm1, __shfl_xor_sync(0xffffffffu, rm1, 2));
        float mn0 = fmaxf(m0, rm0), mn1 = fmaxf(m1, rm1);
        float c0 = __expf(m0 - mn0), c1 = __expf(m1 - mn1);
        float p[8][4];
        float s0 = 0.f, s1 = 0.f;
#pragma unroll
        for (int nt = 0; nt < 8; nt++) {
            p[nt][0] = __expf(sacc[nt][0] - mn0);
            p[nt][1] = __expf(sacc[nt][1] - mn0);
            p[nt][2] = __expf(sacc[nt][2] - mn1);
            p[nt][3] = __expf(sacc[nt][3] - mn1);
            s0 += p[nt][0] + p[nt][1];
            s1 += p[nt][2] + p[nt][3];
        }
        s0 += __shfl_xor_sync(0xffffffffu, s0, 1);
        s0 += __shfl_xor_sync(0xffffffffu, s0, 2);
        s1 += __shfl_xor_sync(0xffffffffu, s1, 1);
        s1 += __shfl_xor_sync(0xffffffffu, s1, 2);
        l0 = l0 * c0 + s0; l1 = l1 * c1 + s1;
        m0 = mn0; m1 = mn1;
#pragma unroll
        for (int nt = 0; nt < 8; nt++) {
            oacc[nt][0] *= c0; oacc[nt][1] *= c0;
            oacc[nt][2] *= c1; oacc[nt][3] *= c1;
        }

        // ---- O += P V ----
#pragma unroll
        for (int j = 0; j < 4; j++) {        // k16 block = S tiles 2j, 2j+1
            uint32_t ph[4], pl[4];
            pack_hl(p[2 * j][0],     p[2 * j][1],     ph[0], pl[0]);
            pack_hl(p[2 * j][2],     p[2 * j][3],     ph[1], pl[1]);
            pack_hl(p[2 * j + 1][0], p[2 * j + 1][1], ph[2], pl[2]);
            pack_hl(p[2 * j + 1][2], p[2 * j + 1][3], ph[3], pl[3]);
#pragma unroll
            for (int ntp = 0; ntp < 4; ntp++) {
                uint32_t ad = vfb + (uint32_t)(j * 16 * FKST) * 2u + ntp * 32;
                uint32_t vh4[4], vl4[4];
                ldsm4t(vh4, ad);
                ldsm4t(vl4, ad + 9216);
                mma16816(oacc[2*ntp],   ph, vh4);
                mma16816(oacc[2*ntp],   pl, vh4);
                mma16816(oacc[2*ntp],   ph, vl4);
                mma16816(oacc[2*ntp+1], ph, vh4 + 2);
                mma16816(oacc[2*ntp+1], pl, vh4 + 2);
                mma16816(oacc[2*ntp+1], ph, vl4 + 2);
            }
        }
    }

    // ---- epilogue ----
    float il0 = 1.f / l0, il1 = 1.f / l1;
    int g = lane >> 2, cc2 = (lane & 3) * 2;
    int row0 = b * TQ + qt * 64 + warp * 16 + g;
#pragma unroll
    for (int nt = 0; nt < 8; nt++) {
        int col = h * HD + nt * 8 + cc2;
        float2 v0 = make_float2(oacc[nt][0] * il0, oacc[nt][1] * il0);
        float2 v1 = make_float2(oacc[nt][2] * il1, oacc[nt][3] * il1);
        *(float2*)&g_att[(size_t)row0 * DMODEL + col] = v0;
        *(float2*)&g_att[(size_t)(row0 + 8) * DMODEL + col] = v1;
    }
}

// ---------------------------------------------------------------------------
extern "C" void kernel_launch(void* const* d_in, const int* in_sizes, int n_in,
                              void* d_out, int out_size)
{
    const float *x = 0, *w_qkv = 0, *w_out = 0, *b_out = 0;
    for (int i = 0; i < n_in; i++) {
        switch (in_sizes[i]) {
            case 4194304: x     = (const float*)d_in[i]; break;
            case 3145728: w_qkv = (const float*)d_in[i]; break;
            case 1048576: w_out = (const float*)d_in[i]; break;
            case 1024:    b_out = (const float*)d_in[i]; break;
        }
    }
    if (!x && n_in >= 4) {
        x     = (const float*)d_in[0];
        w_qkv = (const float*)d_in[1];
        w_out = (const float*)d_in[2];
        b_out = (const float*)d_in[3];
    }
    float* out = (float*)d_out;

    fill_qkv_kernel<<<4096, 256>>>();
    fill_att_kernel<<<2048, 256>>>();
    rope_table_kernel<<<(TQ * 32 + 255) / 256, 256>>>();
    gemm_nt_bf16x3<<<dim3(D3 / 128, BT / 128), 256>>>(
        x, w_qkv, nullptr, nullptr, BT, D3, DMODEL, 0, 1);
    rope_kernel<<<BT, 256>>>();
    flash_tc_kernel<<<dim3(32, 32), 128>>>();
    gemm_nt_bf16x3<<<dim3(DMODEL / 128, BT / 128), 256>>>(
        nullptr, w_out, b_out, out, BT, DMODEL, DMODEL, 1, 0);
}